// round 1
// baseline (speedup 1.0000x reference)
#include <cuda_runtime.h>
#include <math.h>

#define NN 50000
#define NE 800000
#define NT (NE + NN)

// ---------------- scratch (static __device__, allocation-free) ----------------
__device__ float g_h1 [NN * 256];   // layer1 pre-agg features h = x@W1
__device__ float g_h1a[NN * 256];   // layer1 output (after softmax-agg + b1 + elu)
__device__ float g_al1s[NN * 4];
__device__ float g_al1d[NN * 4];
__device__ float g_h2 [NN * 64];    // layer2 pre-agg features
__device__ float g_h2a[NN * 64];    // layer2 output
__device__ float g_al2s[NN];
__device__ float g_al2d[NN];
__device__ int   g_deg[NN];
__device__ int   g_off[NN + 1];
__device__ int   g_cur[NN];
__device__ int   g_row[NT];         // CSR (by destination): source node per slot

__device__ __forceinline__ float lrelu(float v) { return v > 0.f ? v : 0.2f * v; }
__device__ __forceinline__ float elu1(float v)  { return v > 0.f ? v : expm1f(v); }

// ---------------- CSR build ----------------
__global__ void k_deg_init() {
    int i = blockIdx.x * blockDim.x + threadIdx.x;
    if (i < NN) g_deg[i] = 1;  // self-loop
}

__global__ void k_hist(const int* __restrict__ col) {
    int e = blockIdx.x * blockDim.x + threadIdx.x;
    if (e < NE) atomicAdd(&g_deg[col[e]], 1);
}

__global__ void k_scan() {  // single block, 1024 threads
    __shared__ int ss[1024];
    int t = threadIdx.x;
    const int CH = 49;  // 1024*49 >= NN
    int base = t * CH;
    int s = 0;
    for (int i = 0; i < CH; i++) { int idx = base + i; if (idx < NN) s += g_deg[idx]; }
    ss[t] = s;
    __syncthreads();
    for (int d = 1; d < 1024; d <<= 1) {
        int v = 0;
        if (t >= d) v = ss[t - d];
        __syncthreads();
        if (t >= d) ss[t] += v;
        __syncthreads();
    }
    int excl = (t == 0) ? 0 : ss[t - 1];
    for (int i = 0; i < CH; i++) {
        int idx = base + i;
        if (idx < NN) { g_off[idx] = excl; g_cur[idx] = excl; excl += g_deg[idx]; }
    }
    if (t == 1023) g_off[NN] = ss[1023];
}

__global__ void k_scatter(const int* __restrict__ ei) {
    int e = blockIdx.x * blockDim.x + threadIdx.x;
    if (e >= NT) return;
    int r, c;
    if (e < NE) { r = ei[e]; c = ei[NE + e]; } else { r = c = e - NE; }
    int pos = atomicAdd(&g_cur[c], 1);
    g_row[pos] = r;
}

// ---------------- GEMM1: h1 = x[N,64] @ W1[64,256] ----------------
__global__ __launch_bounds__(256) void k_gemm1(const float* __restrict__ x,
                                               const float* __restrict__ W1) {
    __shared__ float xs[32][64];
    int col = threadIdx.x;           // 0..255
    int row0 = blockIdx.x * 32;
    float w[64];
#pragma unroll
    for (int k = 0; k < 64; k++) w[k] = W1[k * 256 + col];
    int nrows = NN - row0; if (nrows > 32) nrows = 32;
    for (int i = threadIdx.x; i < nrows * 64; i += 256)
        xs[i >> 6][i & 63] = x[row0 * 64 + i];
    __syncthreads();
    for (int r = 0; r < nrows; r++) {
        float acc = 0.f;
#pragma unroll
        for (int k = 0; k < 64; k++) acc = fmaf(xs[r][k], w[k], acc);
        g_h1[(row0 + r) * 256 + col] = acc;
    }
}

// ---------------- attention logits layer 1 (warp per node, 4 heads) ----------------
__global__ void k_al1(const float* __restrict__ as, const float* __restrict__ ad) {
    int wid  = (blockIdx.x * blockDim.x + threadIdx.x) >> 5;
    int lane = threadIdx.x & 31;
    if (wid >= NN) return;
    float ps[4] = {0, 0, 0, 0}, pd[4] = {0, 0, 0, 0};
#pragma unroll
    for (int j = 0; j < 8; j++) {
        int h  = j >> 1;
        int cc = lane + 32 * (j & 1);
        float v = g_h1[wid * 256 + h * 64 + cc];
        ps[h] += v * as[h * 64 + cc];
        pd[h] += v * ad[h * 64 + cc];
    }
#pragma unroll
    for (int off = 16; off; off >>= 1) {
#pragma unroll
        for (int h = 0; h < 4; h++) {
            ps[h] += __shfl_xor_sync(0xffffffffu, ps[h], off);
            pd[h] += __shfl_xor_sync(0xffffffffu, pd[h], off);
        }
    }
    if (lane < 4) {
        g_al1s[wid * 4 + lane] = ps[lane];
        g_al1d[wid * 4 + lane] = pd[lane];
    }
}

// ---------------- layer-1 segment softmax + aggregation (warp per dst node) ----------------
__global__ void k_agg1(const float* __restrict__ b1) {
    int n    = (blockIdx.x * blockDim.x + threadIdx.x) >> 5;
    int lane = threadIdx.x & 31;
    if (n >= NN) return;
    int s0 = g_off[n], s1 = g_off[n + 1];
    float4 adv = *(const float4*)&g_al1d[n * 4];
    float ad0 = adv.x, ad1 = adv.y, ad2 = adv.z, ad3 = adv.w;

    // pass 1: per-head max
    float m0 = -1e30f, m1 = -1e30f, m2 = -1e30f, m3 = -1e30f;
    for (int i = s0 + lane; i < s1; i += 32) {
        int r = g_row[i];
        float4 av = *(const float4*)&g_al1s[r * 4];
        m0 = fmaxf(m0, lrelu(av.x + ad0));
        m1 = fmaxf(m1, lrelu(av.y + ad1));
        m2 = fmaxf(m2, lrelu(av.z + ad2));
        m3 = fmaxf(m3, lrelu(av.w + ad3));
    }
#pragma unroll
    for (int off = 16; off; off >>= 1) {
        m0 = fmaxf(m0, __shfl_xor_sync(0xffffffffu, m0, off));
        m1 = fmaxf(m1, __shfl_xor_sync(0xffffffffu, m1, off));
        m2 = fmaxf(m2, __shfl_xor_sync(0xffffffffu, m2, off));
        m3 = fmaxf(m3, __shfl_xor_sync(0xffffffffu, m3, off));
    }

    // pass 2: per-head exp-sum
    float z0 = 0.f, z1 = 0.f, z2 = 0.f, z3 = 0.f;
    for (int i = s0 + lane; i < s1; i += 32) {
        int r = g_row[i];
        float4 av = *(const float4*)&g_al1s[r * 4];
        z0 += __expf(lrelu(av.x + ad0) - m0);
        z1 += __expf(lrelu(av.y + ad1) - m1);
        z2 += __expf(lrelu(av.z + ad2) - m2);
        z3 += __expf(lrelu(av.w + ad3) - m3);
    }
#pragma unroll
    for (int off = 16; off; off >>= 1) {
        z0 += __shfl_xor_sync(0xffffffffu, z0, off);
        z1 += __shfl_xor_sync(0xffffffffu, z1, off);
        z2 += __shfl_xor_sync(0xffffffffu, z2, off);
        z3 += __shfl_xor_sync(0xffffffffu, z3, off);
    }
    float i0 = 1.f / (z0 + 1e-16f), i1 = 1.f / (z1 + 1e-16f);
    float i2 = 1.f / (z2 + 1e-16f), i3 = 1.f / (z3 + 1e-16f);

    // pass 3: weighted accumulate (whole warp per edge, coalesced 256-float rows)
    float acc[8] = {0, 0, 0, 0, 0, 0, 0, 0};
    for (int i = s0; i < s1; i++) {
        int r = g_row[i];  // uniform across warp
        float4 av = *(const float4*)&g_al1s[r * 4];
        float w0 = __expf(lrelu(av.x + ad0) - m0) * i0;
        float w1 = __expf(lrelu(av.y + ad1) - m1) * i1;
        float w2 = __expf(lrelu(av.z + ad2) - m2) * i2;
        float w3 = __expf(lrelu(av.w + ad3) - m3) * i3;
        const float* hr = &g_h1[r * 256];
#pragma unroll
        for (int j = 0; j < 8; j++) {
            int h = j >> 1;
            float w = (h == 0) ? w0 : (h == 1) ? w1 : (h == 2) ? w2 : w3;
            acc[j] = fmaf(w, hr[h * 64 + (j & 1) * 32 + lane], acc[j]);
        }
    }
#pragma unroll
    for (int j = 0; j < 8; j++) {
        int c = (j >> 1) * 64 + (j & 1) * 32 + lane;
        g_h1a[n * 256 + c] = elu1(acc[j] + b1[c]);
    }
}

// ---------------- GEMM2: h2 = h1a[N,256] @ W2[256,64] ----------------
__global__ __launch_bounds__(256) void k_gemm2(const float* __restrict__ W2) {
    __shared__ float xs[16][256];
    __shared__ float red[4][16][64];
    int tid = threadIdx.x;
    int j = tid & 63, q = tid >> 6;       // q: K-quarter
    int row0 = blockIdx.x * 16;
    int nrows = NN - row0; if (nrows > 16) nrows = 16;
    float w[64];
#pragma unroll
    for (int k = 0; k < 64; k++) w[k] = W2[(q * 64 + k) * 64 + j];
    for (int i = tid; i < nrows * 256; i += 256)
        xs[i >> 8][i & 255] = g_h1a[row0 * 256 + i];
    __syncthreads();
    for (int r = 0; r < nrows; r++) {
        float acc = 0.f;
#pragma unroll
        for (int k = 0; k < 64; k++) acc = fmaf(xs[r][q * 64 + k], w[k], acc);
        red[q][r][j] = acc;
    }
    __syncthreads();
    for (int i = tid; i < nrows * 64; i += 256) {
        int r = i >> 6, jj = i & 63;
        g_h2[row0 * 64 + i] = red[0][r][jj] + red[1][r][jj] + red[2][r][jj] + red[3][r][jj];
    }
}

// ---------------- attention logits layer 2 (warp per node, 1 head) ----------------
__global__ void k_al2(const float* __restrict__ as, const float* __restrict__ ad) {
    int wid  = (blockIdx.x * blockDim.x + threadIdx.x) >> 5;
    int lane = threadIdx.x & 31;
    if (wid >= NN) return;
    float v0 = g_h2[wid * 64 + lane], v1 = g_h2[wid * 64 + 32 + lane];
    float ps = v0 * as[lane] + v1 * as[32 + lane];
    float pd = v0 * ad[lane] + v1 * ad[32 + lane];
#pragma unroll
    for (int off = 16; off; off >>= 1) {
        ps += __shfl_xor_sync(0xffffffffu, ps, off);
        pd += __shfl_xor_sync(0xffffffffu, pd, off);
    }
    if (lane == 0) { g_al2s[wid] = ps; g_al2d[wid] = pd; }
}

// ---------------- layer-2 segment softmax + aggregation ----------------
__global__ void k_agg2(const float* __restrict__ b2) {
    int n    = (blockIdx.x * blockDim.x + threadIdx.x) >> 5;
    int lane = threadIdx.x & 31;
    if (n >= NN) return;
    int s0 = g_off[n], s1 = g_off[n + 1];
    float ad = g_al2d[n];

    float m = -1e30f;
    for (int i = s0 + lane; i < s1; i += 32)
        m = fmaxf(m, lrelu(g_al2s[g_row[i]] + ad));
#pragma unroll
    for (int off = 16; off; off >>= 1)
        m = fmaxf(m, __shfl_xor_sync(0xffffffffu, m, off));

    float z = 0.f;
    for (int i = s0 + lane; i < s1; i += 32)
        z += __expf(lrelu(g_al2s[g_row[i]] + ad) - m);
#pragma unroll
    for (int off = 16; off; off >>= 1)
        z += __shfl_xor_sync(0xffffffffu, z, off);
    float inv = 1.f / (z + 1e-16f);

    float a0 = 0.f, a1 = 0.f;
    for (int i = s0; i < s1; i++) {
        int r = g_row[i];
        float w = __expf(lrelu(g_al2s[r] + ad) - m) * inv;
        a0 = fmaf(w, g_h2[r * 64 + lane],      a0);
        a1 = fmaf(w, g_h2[r * 64 + 32 + lane], a1);
    }
    g_h2a[n * 64 + lane]      = elu1(a0 + b2[lane]);
    g_h2a[n * 64 + 32 + lane] = elu1(a1 + b2[32 + lane]);
}

// ---------------- node output: h2a[N,64] @ Wn[64,32] + bn ----------------
__global__ void k_nodeout(const float* __restrict__ Wn, const float* __restrict__ bn,
                          float* __restrict__ out) {
    int n    = (blockIdx.x * blockDim.x + threadIdx.x) >> 5;
    int lane = threadIdx.x & 31;
    if (n >= NN) return;
    float xv0 = g_h2a[n * 64 + lane];
    float xv1 = g_h2a[n * 64 + 32 + lane];
    float acc = bn[lane];
#pragma unroll
    for (int jj = 0; jj < 32; jj++) {
        float xb0 = __shfl_sync(0xffffffffu, xv0, jj);
        float xb1 = __shfl_sync(0xffffffffu, xv1, jj);
        acc = fmaf(xb0, Wn[jj * 32 + lane], acc);
        acc = fmaf(xb1, Wn[(32 + jj) * 32 + lane], acc);
    }
    out[n * 32 + lane] = acc;
}

// ---------------- edge output (warp per original edge) ----------------
__global__ void k_edgeout(const int* __restrict__ ei, const float* __restrict__ ea,
                          const float* __restrict__ We, const float* __restrict__ be,
                          float* __restrict__ out) {
    int e    = (blockIdx.x * blockDim.x + threadIdx.x) >> 5;
    int lane = threadIdx.x & 31;
    if (e >= NE) return;
    int r = ei[e], c = ei[NE + e];
    float t = g_h2a[r * 64 + lane]      * We[lane]
            + g_h2a[r * 64 + 32 + lane] * We[32 + lane]
            + g_h2a[c * 64 + lane]      * We[64 + lane]
            + g_h2a[c * 64 + 32 + lane] * We[96 + lane];
    if (lane < 16) t = fmaf(ea[e * 16 + lane], We[128 + lane], t);
#pragma unroll
    for (int off = 16; off; off >>= 1)
        t += __shfl_xor_sync(0xffffffffu, t, off);
    if (lane == 0) out[NN * 32 + e] = t + be[0];
}

// ---------------- launch ----------------
extern "C" void kernel_launch(void* const* d_in, const int* in_sizes, int n_in,
                              void* d_out, int out_size) {
    const float* x   = (const float*)d_in[0];
    const int*   ei  = (const int*)  d_in[1];
    const float* ea  = (const float*)d_in[2];
    const float* W1  = (const float*)d_in[3];
    const float* a1s = (const float*)d_in[4];
    const float* a1d = (const float*)d_in[5];
    const float* b1  = (const float*)d_in[6];
    const float* W2  = (const float*)d_in[7];
    const float* a2s = (const float*)d_in[8];
    const float* a2d = (const float*)d_in[9];
    const float* b2  = (const float*)d_in[10];
    const float* Wn  = (const float*)d_in[11];
    const float* bn  = (const float*)d_in[12];
    const float* We  = (const float*)d_in[13];
    const float* be  = (const float*)d_in[14];
    float* out = (float*)d_out;

    // CSR build (by destination), includes self-loops
    k_deg_init<<<(NN + 255) / 256, 256>>>();
    k_hist   <<<(NE + 255) / 256, 256>>>(ei + NE);
    k_scan   <<<1, 1024>>>();
    k_scatter<<<(NT + 255) / 256, 256>>>(ei);

    // Layer 1
    k_gemm1<<<(NN + 31) / 32, 256>>>(x, W1);
    k_al1  <<<(NN * 32 + 255) / 256, 256>>>(a1s, a1d);
    k_agg1 <<<(NN * 32 + 255) / 256, 256>>>(b1);

    // Layer 2
    k_gemm2<<<(NN + 15) / 16, 256>>>(W2);
    k_al2  <<<(NN * 32 + 255) / 256, 256>>>(a2s, a2d);
    k_agg2 <<<(NN * 32 + 255) / 256, 256>>>(b2);

    // Outputs
    k_nodeout<<<(NN * 32 + 255) / 256, 256>>>(Wn, bn, out);
    k_edgeout<<<(NE * 32 + 255) / 256, 256>>>(ei, ea, We, be, out);
}

// round 2
// speedup vs baseline: 1.1811x; 1.1811x over previous
#include <cuda_runtime.h>
#include <math.h>

#define NN 50000
#define NE 800000
#define NT (NE + NN)

// ---------------- scratch (static __device__, allocation-free) ----------------
__device__ float  g_h1 [NN * 256];   // layer1 pre-agg features h = x@W1
__device__ float  g_h1a[NN * 256];   // layer1 output (after softmax-agg + b1 + elu)
__device__ float  g_al1s[NN * 4];
__device__ float  g_al1d[NN * 4];
__device__ float  g_h2 [NN * 64];    // layer2 pre-agg features
__device__ float  g_h2a[NN * 64];    // layer2 output
__device__ float  g_al2s[NN];
__device__ float  g_al2d[NN];
__device__ float  g_u[NN];           // dot(h2a[n], We[0:64])
__device__ float  g_v[NN];           // dot(h2a[n], We[64:128])
__device__ int    g_deg[NN];
__device__ int    g_off[NN + 1];
__device__ int    g_cur[NN];
__device__ int    g_row[NT];         // CSR (by destination): source node per slot
__device__ float4 g_alpha1[NT];      // normalized layer-1 attention per slot (4 heads)
__device__ float  g_alpha2[NT];      // normalized layer-2 attention per slot

__device__ __forceinline__ float lrelu(float v) { return v > 0.f ? v : 0.2f * v; }
__device__ __forceinline__ float elu1(float v)  { return v > 0.f ? v : expm1f(v); }

// ---------------- CSR build ----------------
__global__ void k_deg_init() {
    int i = blockIdx.x * blockDim.x + threadIdx.x;
    if (i < NN) g_deg[i] = 1;  // self-loop
}

__global__ void k_hist(const int* __restrict__ col) {
    int e = blockIdx.x * blockDim.x + threadIdx.x;
    if (e < NE) atomicAdd(&g_deg[col[e]], 1);
}

__global__ void k_scan() {  // single block, 1024 threads
    __shared__ int ss[1024];
    int t = threadIdx.x;
    const int CH = 49;  // 1024*49 >= NN
    int base = t * CH;
    int s = 0;
#pragma unroll
    for (int i = 0; i < CH; i++) { int idx = base + i; if (idx < NN) s += g_deg[idx]; }
    ss[t] = s;
    __syncthreads();
    for (int d = 1; d < 1024; d <<= 1) {
        int v = 0;
        if (t >= d) v = ss[t - d];
        __syncthreads();
        if (t >= d) ss[t] += v;
        __syncthreads();
    }
    int excl = (t == 0) ? 0 : ss[t - 1];
#pragma unroll
    for (int i = 0; i < CH; i++) {
        int idx = base + i;
        if (idx < NN) { g_off[idx] = excl; g_cur[idx] = excl; excl += g_deg[idx]; }
    }
    if (t == 1023) g_off[NN] = ss[1023];
}

__global__ void k_scatter(const int* __restrict__ ei) {
    int e = blockIdx.x * blockDim.x + threadIdx.x;
    if (e >= NT) return;
    int r, c;
    if (e < NE) { r = ei[e]; c = ei[NE + e]; } else { r = c = e - NE; }
    int pos = atomicAdd(&g_cur[c], 1);
    g_row[pos] = r;
}

// ---------------- GEMM1: h1 = x[N,64] @ W1[64,256] ----------------
__global__ __launch_bounds__(256) void k_gemm1(const float* __restrict__ x,
                                               const float* __restrict__ W1) {
    __shared__ float xs[32][64];
    int col = threadIdx.x;           // 0..255
    int row0 = blockIdx.x * 32;
    float w[64];
#pragma unroll
    for (int k = 0; k < 64; k++) w[k] = W1[k * 256 + col];
    int nrows = NN - row0; if (nrows > 32) nrows = 32;
    for (int i = threadIdx.x; i < nrows * 64; i += 256)
        xs[i >> 6][i & 63] = x[row0 * 64 + i];
    __syncthreads();
    for (int r = 0; r < nrows; r++) {
        float acc = 0.f;
#pragma unroll
        for (int k = 0; k < 64; k++) acc = fmaf(xs[r][k], w[k], acc);
        g_h1[(row0 + r) * 256 + col] = acc;
    }
}

// ---------------- attention logits layer 1 (warp per node, 4 heads) ----------------
__global__ void k_al1(const float* __restrict__ as, const float* __restrict__ ad) {
    int wid  = (blockIdx.x * blockDim.x + threadIdx.x) >> 5;
    int lane = threadIdx.x & 31;
    if (wid >= NN) return;
    float ps[4] = {0, 0, 0, 0}, pd[4] = {0, 0, 0, 0};
#pragma unroll
    for (int j = 0; j < 8; j++) {
        int h  = j >> 1;
        int cc = lane + 32 * (j & 1);
        float v = g_h1[wid * 256 + h * 64 + cc];
        ps[h] += v * as[h * 64 + cc];
        pd[h] += v * ad[h * 64 + cc];
    }
#pragma unroll
    for (int off = 16; off; off >>= 1) {
#pragma unroll
        for (int h = 0; h < 4; h++) {
            ps[h] += __shfl_xor_sync(0xffffffffu, ps[h], off);
            pd[h] += __shfl_xor_sync(0xffffffffu, pd[h], off);
        }
    }
    if (lane < 4) {
        g_al1s[wid * 4 + lane] = ps[lane];
        g_al1d[wid * 4 + lane] = pd[lane];
    }
}

// ---------------- layer-1 softmax weights per slot (warp per dst node) ----------------
__global__ void k_msz1() {
    int n    = (blockIdx.x * blockDim.x + threadIdx.x) >> 5;
    int lane = threadIdx.x & 31;
    if (n >= NN) return;
    int s0 = g_off[n], s1 = g_off[n + 1];
    float4 adv = *(const float4*)&g_al1d[n * 4];

    // pass 1: per-head max
    float m0 = -1e30f, m1 = -1e30f, m2 = -1e30f, m3 = -1e30f;
    for (int i = s0 + lane; i < s1; i += 32) {
        int r = g_row[i];
        float4 av = *(const float4*)&g_al1s[r * 4];
        m0 = fmaxf(m0, lrelu(av.x + adv.x));
        m1 = fmaxf(m1, lrelu(av.y + adv.y));
        m2 = fmaxf(m2, lrelu(av.z + adv.z));
        m3 = fmaxf(m3, lrelu(av.w + adv.w));
    }
#pragma unroll
    for (int off = 16; off; off >>= 1) {
        m0 = fmaxf(m0, __shfl_xor_sync(0xffffffffu, m0, off));
        m1 = fmaxf(m1, __shfl_xor_sync(0xffffffffu, m1, off));
        m2 = fmaxf(m2, __shfl_xor_sync(0xffffffffu, m2, off));
        m3 = fmaxf(m3, __shfl_xor_sync(0xffffffffu, m3, off));
    }

    // pass 2: exp, store unnormalized, accumulate z
    float z0 = 0.f, z1 = 0.f, z2 = 0.f, z3 = 0.f;
    for (int i = s0 + lane; i < s1; i += 32) {
        int r = g_row[i];
        float4 av = *(const float4*)&g_al1s[r * 4];
        float4 e;
        e.x = __expf(lrelu(av.x + adv.x) - m0);
        e.y = __expf(lrelu(av.y + adv.y) - m1);
        e.z = __expf(lrelu(av.z + adv.z) - m2);
        e.w = __expf(lrelu(av.w + adv.w) - m3);
        z0 += e.x; z1 += e.y; z2 += e.z; z3 += e.w;
        g_alpha1[i] = e;
    }
#pragma unroll
    for (int off = 16; off; off >>= 1) {
        z0 += __shfl_xor_sync(0xffffffffu, z0, off);
        z1 += __shfl_xor_sync(0xffffffffu, z1, off);
        z2 += __shfl_xor_sync(0xffffffffu, z2, off);
        z3 += __shfl_xor_sync(0xffffffffu, z3, off);
    }
    float i0 = 1.f / (z0 + 1e-16f), i1 = 1.f / (z1 + 1e-16f);
    float i2 = 1.f / (z2 + 1e-16f), i3 = 1.f / (z3 + 1e-16f);

    // pass 3: normalize in place
    for (int i = s0 + lane; i < s1; i += 32) {
        float4 e = g_alpha1[i];
        e.x *= i0; e.y *= i1; e.z *= i2; e.w *= i3;
        g_alpha1[i] = e;
    }
}

// ---------------- layer-1 aggregation (warp per dst node, float4, prefetch) -------
__global__ void k_agg1(const float* __restrict__ b1) {
    int n    = (blockIdx.x * blockDim.x + threadIdx.x) >> 5;
    int lane = threadIdx.x & 31;
    if (n >= NN) return;
    int s0 = g_off[n], s1 = g_off[n + 1];

    float4 acc0 = {0, 0, 0, 0}, acc1 = {0, 0, 0, 0};
    int    r = g_row[s0];        // degree >= 1 always (self-loop)
    float4 a = g_alpha1[s0];
    for (int i = s0; i < s1; i++) {
        int rn = r; float4 an = a;
        if (i + 1 < s1) { rn = g_row[i + 1]; an = g_alpha1[i + 1]; }
        const float4* hr = (const float4*)(g_h1 + (size_t)r * 256);
        float4 h0 = hr[lane];
        float4 h1v = hr[32 + lane];
        float wa = (lane < 16) ? a.x : a.y;   // cols [0,128):   head = lane>>4
        float wb = (lane < 16) ? a.z : a.w;   // cols [128,256): head = 2 + lane>>4
        acc0.x = fmaf(wa, h0.x, acc0.x);  acc0.y = fmaf(wa, h0.y, acc0.y);
        acc0.z = fmaf(wa, h0.z, acc0.z);  acc0.w = fmaf(wa, h0.w, acc0.w);
        acc1.x = fmaf(wb, h1v.x, acc1.x); acc1.y = fmaf(wb, h1v.y, acc1.y);
        acc1.z = fmaf(wb, h1v.z, acc1.z); acc1.w = fmaf(wb, h1v.w, acc1.w);
        r = rn; a = an;
    }
    float4 bv0 = *(const float4*)(b1 + 4 * lane);
    float4 bv1 = *(const float4*)(b1 + 128 + 4 * lane);
    float4 o0, o1;
    o0.x = elu1(acc0.x + bv0.x); o0.y = elu1(acc0.y + bv0.y);
    o0.z = elu1(acc0.z + bv0.z); o0.w = elu1(acc0.w + bv0.w);
    o1.x = elu1(acc1.x + bv1.x); o1.y = elu1(acc1.y + bv1.y);
    o1.z = elu1(acc1.z + bv1.z); o1.w = elu1(acc1.w + bv1.w);
    float4* dst = (float4*)(g_h1a + (size_t)n * 256);
    dst[lane] = o0;
    dst[32 + lane] = o1;
}

// ---------------- GEMM2: h2 = h1a[N,256] @ W2[256,64] ----------------
__global__ __launch_bounds__(256) void k_gemm2(const float* __restrict__ W2) {
    __shared__ float xs[16][256];
    __shared__ float red[4][16][64];
    int tid = threadIdx.x;
    int j = tid & 63, q = tid >> 6;       // q: K-quarter
    int row0 = blockIdx.x * 16;
    int nrows = NN - row0; if (nrows > 16) nrows = 16;
    float w[64];
#pragma unroll
    for (int k = 0; k < 64; k++) w[k] = W2[(q * 64 + k) * 64 + j];
    for (int i = tid; i < nrows * 256; i += 256)
        xs[i >> 8][i & 255] = g_h1a[row0 * 256 + i];
    __syncthreads();
    for (int r = 0; r < nrows; r++) {
        float acc = 0.f;
#pragma unroll
        for (int k = 0; k < 64; k++) acc = fmaf(xs[r][q * 64 + k], w[k], acc);
        red[q][r][j] = acc;
    }
    __syncthreads();
    for (int i = tid; i < nrows * 64; i += 256) {
        int r = i >> 6, jj = i & 63;
        g_h2[row0 * 64 + i] = red[0][r][jj] + red[1][r][jj] + red[2][r][jj] + red[3][r][jj];
    }
}

// ---------------- attention logits layer 2 (warp per node, 1 head) ----------------
__global__ void k_al2(const float* __restrict__ as, const float* __restrict__ ad) {
    int wid  = (blockIdx.x * blockDim.x + threadIdx.x) >> 5;
    int lane = threadIdx.x & 31;
    if (wid >= NN) return;
    float v0 = g_h2[wid * 64 + lane], v1 = g_h2[wid * 64 + 32 + lane];
    float ps = v0 * as[lane] + v1 * as[32 + lane];
    float pd = v0 * ad[lane] + v1 * ad[32 + lane];
#pragma unroll
    for (int off = 16; off; off >>= 1) {
        ps += __shfl_xor_sync(0xffffffffu, ps, off);
        pd += __shfl_xor_sync(0xffffffffu, pd, off);
    }
    if (lane == 0) { g_al2s[wid] = ps; g_al2d[wid] = pd; }
}

// ---------------- layer-2 softmax weights per slot ----------------
__global__ void k_msz2() {
    int n    = (blockIdx.x * blockDim.x + threadIdx.x) >> 5;
    int lane = threadIdx.x & 31;
    if (n >= NN) return;
    int s0 = g_off[n], s1 = g_off[n + 1];
    float ad = g_al2d[n];

    float m = -1e30f;
    for (int i = s0 + lane; i < s1; i += 32)
        m = fmaxf(m, lrelu(g_al2s[g_row[i]] + ad));
#pragma unroll
    for (int off = 16; off; off >>= 1)
        m = fmaxf(m, __shfl_xor_sync(0xffffffffu, m, off));

    float z = 0.f;
    for (int i = s0 + lane; i < s1; i += 32) {
        float e = __expf(lrelu(g_al2s[g_row[i]] + ad) - m);
        z += e;
        g_alpha2[i] = e;
    }
#pragma unroll
    for (int off = 16; off; off >>= 1)
        z += __shfl_xor_sync(0xffffffffu, z, off);
    float inv = 1.f / (z + 1e-16f);

    for (int i = s0 + lane; i < s1; i += 32)
        g_alpha2[i] *= inv;
}

// ---------------- layer-2 aggregation (warp per dst node, float2, prefetch) -------
__global__ void k_agg2(const float* __restrict__ b2) {
    int n    = (blockIdx.x * blockDim.x + threadIdx.x) >> 5;
    int lane = threadIdx.x & 31;
    if (n >= NN) return;
    int s0 = g_off[n], s1 = g_off[n + 1];

    float2 acc = {0, 0};
    int   r = g_row[s0];
    float a = g_alpha2[s0];
    for (int i = s0; i < s1; i++) {
        int rn = r; float an = a;
        if (i + 1 < s1) { rn = g_row[i + 1]; an = g_alpha2[i + 1]; }
        float2 h = ((const float2*)(g_h2 + (size_t)r * 64))[lane];
        acc.x = fmaf(a, h.x, acc.x);
        acc.y = fmaf(a, h.y, acc.y);
        r = rn; a = an;
    }
    float2 bv = ((const float2*)b2)[lane];
    float2 o;
    o.x = elu1(acc.x + bv.x);
    o.y = elu1(acc.y + bv.y);
    ((float2*)(g_h2a + (size_t)n * 64))[lane] = o;
}

// ---------------- node output + edge-head factors u,v ----------------
__global__ void k_nodeout(const float* __restrict__ Wn, const float* __restrict__ bn,
                          const float* __restrict__ We, float* __restrict__ out) {
    int n    = (blockIdx.x * blockDim.x + threadIdx.x) >> 5;
    int lane = threadIdx.x & 31;
    if (n >= NN) return;
    float xv0 = g_h2a[n * 64 + lane];
    float xv1 = g_h2a[n * 64 + 32 + lane];

    // edge-head factors: u = h2a[n]·We[0:64], v = h2a[n]·We[64:128]
    float up = xv0 * We[lane]      + xv1 * We[32 + lane];
    float vp = xv0 * We[64 + lane] + xv1 * We[96 + lane];
#pragma unroll
    for (int off = 16; off; off >>= 1) {
        up += __shfl_xor_sync(0xffffffffu, up, off);
        vp += __shfl_xor_sync(0xffffffffu, vp, off);
    }
    if (lane == 0) { g_u[n] = up; g_v[n] = vp; }

    float acc = bn[lane];
#pragma unroll
    for (int jj = 0; jj < 32; jj++) {
        float xb0 = __shfl_sync(0xffffffffu, xv0, jj);
        float xb1 = __shfl_sync(0xffffffffu, xv1, jj);
        acc = fmaf(xb0, Wn[jj * 32 + lane], acc);
        acc = fmaf(xb1, Wn[(32 + jj) * 32 + lane], acc);
    }
    out[n * 32 + lane] = acc;
}

// ---------------- edge output (thread per edge) ----------------
__global__ void k_edgeout(const int* __restrict__ ei, const float* __restrict__ ea,
                          const float* __restrict__ We, const float* __restrict__ be,
                          float* __restrict__ out) {
    int e = blockIdx.x * blockDim.x + threadIdx.x;
    if (e >= NE) return;
    int r = ei[e], c = ei[NE + e];
    float t = g_u[r] + g_v[c] + be[0];
    const float4* eav = (const float4*)(ea + (size_t)e * 16);
    const float4* wev = (const float4*)(We + 128);
    float4 w0 = wev[0], w1 = wev[1], w2 = wev[2], w3 = wev[3];
    float4 e0 = eav[0], e1 = eav[1], e2 = eav[2], e3 = eav[3];
    t += e0.x * w0.x + e0.y * w0.y + e0.z * w0.z + e0.w * w0.w;
    t += e1.x * w1.x + e1.y * w1.y + e1.z * w1.z + e1.w * w1.w;
    t += e2.x * w2.x + e2.y * w2.y + e2.z * w2.z + e2.w * w2.w;
    t += e3.x * w3.x + e3.y * w3.y + e3.z * w3.z + e3.w * w3.w;
    out[NN * 32 + e] = t;
}

// ---------------- launch ----------------
extern "C" void kernel_launch(void* const* d_in, const int* in_sizes, int n_in,
                              void* d_out, int out_size) {
    const float* x   = (const float*)d_in[0];
    const int*   ei  = (const int*)  d_in[1];
    const float* ea  = (const float*)d_in[2];
    const float* W1  = (const float*)d_in[3];
    const float* a1s = (const float*)d_in[4];
    const float* a1d = (const float*)d_in[5];
    const float* b1  = (const float*)d_in[6];
    const float* W2  = (const float*)d_in[7];
    const float* a2s = (const float*)d_in[8];
    const float* a2d = (const float*)d_in[9];
    const float* b2  = (const float*)d_in[10];
    const float* Wn  = (const float*)d_in[11];
    const float* bn  = (const float*)d_in[12];
    const float* We  = (const float*)d_in[13];
    const float* be  = (const float*)d_in[14];
    float* out = (float*)d_out;

    // CSR build (by destination), includes self-loops
    k_deg_init<<<(NN + 255) / 256, 256>>>();
    k_hist   <<<(NE + 255) / 256, 256>>>(ei + NE);
    k_scan   <<<1, 1024>>>();
    k_scatter<<<(NT + 255) / 256, 256>>>(ei);

    // Layer 1
    k_gemm1<<<(NN + 31) / 32, 256>>>(x, W1);
    k_al1  <<<(NN * 32 + 255) / 256, 256>>>(a1s, a1d);
    k_msz1 <<<(NN * 32 + 255) / 256, 256>>>();
    k_agg1 <<<(NN * 32 + 255) / 256, 256>>>(b1);

    // Layer 2
    k_gemm2<<<(NN + 15) / 16, 256>>>(W2);
    k_al2  <<<(NN * 32 + 255) / 256, 256>>>(a2s, a2d);
    k_msz2 <<<(NN * 32 + 255) / 256, 256>>>();
    k_agg2 <<<(NN * 32 + 255) / 256, 256>>>(b2);

    // Outputs
    k_nodeout<<<(NN * 32 + 255) / 256, 256>>>(Wn, bn, We, out);
    k_edgeout<<<(NE + 255) / 256, 256>>>(ei, ea, We, be, out);
}

// round 3
// speedup vs baseline: 1.4896x; 1.2612x over previous
#include <cuda_runtime.h>
#include <cuda_fp16.h>
#include <math.h>

#define NN 50000
#define NE 800000
#define NT (NE + NN)
#define NB 196   // 196*256 = 50176 >= NN

// ---------------- scratch (static __device__, allocation-free) ----------------
__device__ __half g_h1h[NN * 256];   // layer1 pre-agg features (fp16)
__device__ float  g_h1a[NN * 256];   // layer1 output (post agg + b1 + elu)
__device__ float  g_wt1[8 * 64];     // folded W1@a1 (4 src heads, 4 dst heads)
__device__ float  g_al1s[NN * 4];
__device__ float  g_al1d[NN * 4];
__device__ float  g_inv1[NN * 4];    // per-node per-head 1/z
__device__ float  g_h2 [NN * 64];    // layer2 pre-agg features
__device__ float  g_al2s[NN];
__device__ float  g_al2d[NN];
__device__ float  g_inv2[NN];
__device__ float  g_u[NN];           // dot(h2a[n], We[0:64])
__device__ float  g_v[NN];           // dot(h2a[n], We[64:128])
__device__ int    g_deg[NN];
__device__ int    g_off[NN + 1];
__device__ int    g_cur[NN];
__device__ int    g_bsum[NB];
__device__ int    g_bbase[NB];
__device__ int    g_row[NT];         // CSR (by destination): source node per slot
__device__ float4 g_alpha1[NT];      // UNNORMALIZED layer-1 attention exps (4 heads)
__device__ float  g_alpha2[NT];      // UNNORMALIZED layer-2 attention exps

__device__ __forceinline__ float lrelu(float v) { return v > 0.f ? v : 0.2f * v; }
__device__ __forceinline__ float elu1(float v)  { return v > 0.f ? v : expm1f(v); }

// ---------------- CSR build ----------------
__global__ void k_deg_init() {
    int i = blockIdx.x * blockDim.x + threadIdx.x;
    if (i < NN) g_deg[i] = 1;  // self-loop
}

__global__ void k_hist(const int* __restrict__ col) {
    int e = blockIdx.x * blockDim.x + threadIdx.x;
    if (e < NE) atomicAdd(&g_deg[col[e]], 1);
}

__global__ void k_scanA() {  // grid NB, block 256: per-block exclusive scan
    __shared__ int ss[256];
    int b = blockIdx.x, t = threadIdx.x, i = b * 256 + t;
    int d = (i < NN) ? g_deg[i] : 0;
    ss[t] = d; __syncthreads();
    for (int o = 1; o < 256; o <<= 1) {
        int v = 0; if (t >= o) v = ss[t - o];
        __syncthreads();
        if (t >= o) ss[t] += v;
        __syncthreads();
    }
    if (i < NN) g_off[i] = ss[t] - d;
    if (t == 255) g_bsum[b] = ss[255];
}

__global__ void k_scanB() {  // 1 block 256: scan of block sums
    __shared__ int ss[256];
    int t = threadIdx.x;
    int v = (t < NB) ? g_bsum[t] : 0;
    ss[t] = v; __syncthreads();
    for (int o = 1; o < 256; o <<= 1) {
        int u = 0; if (t >= o) u = ss[t - o];
        __syncthreads();
        if (t >= o) ss[t] += u;
        __syncthreads();
    }
    if (t < NB) g_bbase[t] = ss[t] - v;
    if (t == NB - 1) g_off[NN] = ss[t];
}

__global__ void k_scanC() {  // grid NB: add block bases
    int b = blockIdx.x, i = b * 256 + threadIdx.x;
    if (i < NN) {
        int v = g_off[i] + g_bbase[b];
        g_off[i] = v; g_cur[i] = v;
    }
}

__global__ void k_scatter(const int* __restrict__ ei) {
    int e = blockIdx.x * blockDim.x + threadIdx.x;
    if (e >= NT) return;
    int r, c;
    if (e < NE) { r = ei[e]; c = ei[NE + e]; } else { r = c = e - NE; }
    int pos = atomicAdd(&g_cur[c], 1);
    g_row[pos] = r;
}

// ---------------- folded attention weights: wt1[o][k] = sum_c W1[k, h*64+c]*a[h][c] --
__global__ void k_prew(const float* __restrict__ W1, const float* __restrict__ a1s,
                       const float* __restrict__ a1d) {
    int t = threadIdx.x;   // 512 threads, 1 block
    if (t >= 512) return;
    int o = t >> 6, k = t & 63;
    int hh = o & 3;
    const float* a = (o < 4) ? a1s : a1d;
    float s = 0.f;
#pragma unroll 8
    for (int c = 0; c < 64; c++) s += W1[k * 256 + hh * 64 + c] * a[hh * 64 + c];
    g_wt1[o * 64 + k] = s;
}

// ---------------- layer-1 attention logits directly from x (warp per node) --------
__global__ __launch_bounds__(256) void k_al1x(const float* __restrict__ x) {
    __shared__ float ws[8][64];
    int tid = threadIdx.x;
    for (int i = tid; i < 512; i += 256) ws[i >> 6][i & 63] = g_wt1[i];
    __syncthreads();
    int n = blockIdx.x * 8 + (tid >> 5);
    int lane = tid & 31;
    if (n >= NN) return;
    float xv0 = x[n * 64 + lane], xv1 = x[n * 64 + 32 + lane];
    float p[8];
#pragma unroll
    for (int o = 0; o < 8; o++) p[o] = xv0 * ws[o][lane] + xv1 * ws[o][32 + lane];
#pragma unroll
    for (int off = 16; off; off >>= 1)
#pragma unroll
        for (int o = 0; o < 8; o++) p[o] += __shfl_xor_sync(0xffffffffu, p[o], off);
    if (lane == 0) {
        *(float4*)&g_al1s[n * 4] = make_float4(p[0], p[1], p[2], p[3]);
        *(float4*)&g_al1d[n * 4] = make_float4(p[4], p[5], p[6], p[7]);
    }
}

// ---------------- GEMM1: h1 = x[N,64] @ W1[64,256], store fp16 ----------------
__global__ __launch_bounds__(256) void k_gemm1(const float* __restrict__ x,
                                               const float* __restrict__ W1) {
    __shared__ float xs[32][64];
    int col = threadIdx.x;           // 0..255
    int row0 = blockIdx.x * 32;
    float w[64];
#pragma unroll
    for (int k = 0; k < 64; k++) w[k] = W1[k * 256 + col];
    int nrows = NN - row0; if (nrows > 32) nrows = 32;
    for (int i = threadIdx.x; i < nrows * 64; i += 256)
        xs[i >> 6][i & 63] = x[row0 * 64 + i];
    __syncthreads();
    for (int r = 0; r < nrows; r++) {
        float acc = 0.f;
#pragma unroll
        for (int k = 0; k < 64; k++) acc = fmaf(xs[r][k], w[k], acc);
        g_h1h[(size_t)(row0 + r) * 256 + col] = __float2half_rn(acc);
    }
}

// ---------------- layer-1 softmax exps + 1/z (single pass, warp per dst) ----------
__global__ void k_msz1() {
    int n    = (blockIdx.x * blockDim.x + threadIdx.x) >> 5;
    int lane = threadIdx.x & 31;
    if (n >= NN) return;
    int s0 = g_off[n], s1 = g_off[n + 1];
    float4 adv = *(const float4*)&g_al1d[n * 4];

    float z0 = 0.f, z1 = 0.f, z2 = 0.f, z3 = 0.f;
    for (int i = s0 + lane; i < s1; i += 32) {
        int r = g_row[i];
        float4 av = *(const float4*)&g_al1s[r * 4];
        float4 e;
        e.x = __expf(lrelu(av.x + adv.x));
        e.y = __expf(lrelu(av.y + adv.y));
        e.z = __expf(lrelu(av.z + adv.z));
        e.w = __expf(lrelu(av.w + adv.w));
        g_alpha1[i] = e;
        z0 += e.x; z1 += e.y; z2 += e.z; z3 += e.w;
    }
#pragma unroll
    for (int off = 16; off; off >>= 1) {
        z0 += __shfl_xor_sync(0xffffffffu, z0, off);
        z1 += __shfl_xor_sync(0xffffffffu, z1, off);
        z2 += __shfl_xor_sync(0xffffffffu, z2, off);
        z3 += __shfl_xor_sync(0xffffffffu, z3, off);
    }
    if (lane == 0)
        *(float4*)&g_inv1[n * 4] = make_float4(1.f / (z0 + 1e-16f), 1.f / (z1 + 1e-16f),
                                               1.f / (z2 + 1e-16f), 1.f / (z3 + 1e-16f));
}

// ---------------- layer-1 aggregation (warp per dst node, fp16 rows) --------------
__global__ void k_agg1(const float* __restrict__ b1) {
    int n    = (blockIdx.x * blockDim.x + threadIdx.x) >> 5;
    int lane = threadIdx.x & 31;
    if (n >= NN) return;
    int s0 = g_off[n], s1 = g_off[n + 1];
    int h = lane >> 3;  // this lane's 8 columns [lane*8, lane*8+8) all in head h

    float acc[8] = {0, 0, 0, 0, 0, 0, 0, 0};
    int    r = g_row[s0];        // degree >= 1 always (self-loop)
    float4 a = g_alpha1[s0];
    for (int i = s0; i < s1; i++) {
        int rn = r; float4 an = a;
        if (i + 1 < s1) { rn = g_row[i + 1]; an = g_alpha1[i + 1]; }
        float4 raw = ((const float4*)(g_h1h + (size_t)r * 256))[lane];
        float w = (h == 0) ? a.x : (h == 1) ? a.y : (h == 2) ? a.z : a.w;
        const __half2* hp = (const __half2*)&raw;
#pragma unroll
        for (int j = 0; j < 4; j++) {
            float2 f = __half22float2(hp[j]);
            acc[2 * j]     = fmaf(w, f.x, acc[2 * j]);
            acc[2 * j + 1] = fmaf(w, f.y, acc[2 * j + 1]);
        }
        r = rn; a = an;
    }
    float inv = g_inv1[n * 4 + h];
    float4 bv0 = *(const float4*)(b1 + lane * 8);
    float4 bv1 = *(const float4*)(b1 + lane * 8 + 4);
    float4 o0, o1;
    o0.x = elu1(acc[0] * inv + bv0.x); o0.y = elu1(acc[1] * inv + bv0.y);
    o0.z = elu1(acc[2] * inv + bv0.z); o0.w = elu1(acc[3] * inv + bv0.w);
    o1.x = elu1(acc[4] * inv + bv1.x); o1.y = elu1(acc[5] * inv + bv1.y);
    o1.z = elu1(acc[6] * inv + bv1.z); o1.w = elu1(acc[7] * inv + bv1.w);
    float4* dst = (float4*)(g_h1a + (size_t)n * 256 + lane * 8);
    dst[0] = o0;
    dst[1] = o1;
}

// ---------------- GEMM2: h2 = h1a[N,256] @ W2[256,64] ----------------
__global__ __launch_bounds__(256) void k_gemm2(const float* __restrict__ W2) {
    __shared__ float xs[16][256];
    __shared__ float red[4][16][64];
    int tid = threadIdx.x;
    int j = tid & 63, q = tid >> 6;       // q: K-quarter
    int row0 = blockIdx.x * 16;
    int nrows = NN - row0; if (nrows > 16) nrows = 16;
    float w[64];
#pragma unroll
    for (int k = 0; k < 64; k++) w[k] = W2[(q * 64 + k) * 64 + j];
    for (int i = tid; i < nrows * 256; i += 256)
        xs[i >> 8][i & 255] = g_h1a[row0 * 256 + i];
    __syncthreads();
    for (int r = 0; r < nrows; r++) {
        float acc = 0.f;
#pragma unroll
        for (int k = 0; k < 64; k++) acc = fmaf(xs[r][q * 64 + k], w[k], acc);
        red[q][r][j] = acc;
    }
    __syncthreads();
    for (int i = tid; i < nrows * 64; i += 256) {
        int r = i >> 6, jj = i & 63;
        g_h2[row0 * 64 + i] = red[0][r][jj] + red[1][r][jj] + red[2][r][jj] + red[3][r][jj];
    }
}

// ---------------- attention logits layer 2 (warp per node, 1 head) ----------------
__global__ void k_al2(const float* __restrict__ as, const float* __restrict__ ad) {
    int wid  = (blockIdx.x * blockDim.x + threadIdx.x) >> 5;
    int lane = threadIdx.x & 31;
    if (wid >= NN) return;
    float v0 = g_h2[wid * 64 + lane], v1 = g_h2[wid * 64 + 32 + lane];
    float ps = v0 * as[lane] + v1 * as[32 + lane];
    float pd = v0 * ad[lane] + v1 * ad[32 + lane];
#pragma unroll
    for (int off = 16; off; off >>= 1) {
        ps += __shfl_xor_sync(0xffffffffu, ps, off);
        pd += __shfl_xor_sync(0xffffffffu, pd, off);
    }
    if (lane == 0) { g_al2s[wid] = ps; g_al2d[wid] = pd; }
}

// ---------------- layer-2 softmax exps + 1/z (single pass) ----------------
__global__ void k_msz2() {
    int n    = (blockIdx.x * blockDim.x + threadIdx.x) >> 5;
    int lane = threadIdx.x & 31;
    if (n >= NN) return;
    int s0 = g_off[n], s1 = g_off[n + 1];
    float ad = g_al2d[n];

    float z = 0.f;
    for (int i = s0 + lane; i < s1; i += 32) {
        float e = __expf(lrelu(g_al2s[g_row[i]] + ad));
        g_alpha2[i] = e;
        z += e;
    }
#pragma unroll
    for (int off = 16; off; off >>= 1)
        z += __shfl_xor_sync(0xffffffffu, z, off);
    if (lane == 0) g_inv2[n] = 1.f / (z + 1e-16f);
}

// ------- layer-2 aggregation fused with node output + edge factors (warp/node) ----
__global__ void k_agg2out(const float* __restrict__ b2, const float* __restrict__ Wn,
                          const float* __restrict__ bn, const float* __restrict__ We,
                          float* __restrict__ out) {
    int n    = (blockIdx.x * blockDim.x + threadIdx.x) >> 5;
    int lane = threadIdx.x & 31;
    if (n >= NN) return;
    int s0 = g_off[n], s1 = g_off[n + 1];

    float2 acc = {0, 0};
    int   r = g_row[s0];
    float a = g_alpha2[s0];
    for (int i = s0; i < s1; i++) {
        int rn = r; float an = a;
        if (i + 1 < s1) { rn = g_row[i + 1]; an = g_alpha2[i + 1]; }
        float2 h = ((const float2*)(g_h2 + (size_t)r * 64))[lane];
        acc.x = fmaf(a, h.x, acc.x);
        acc.y = fmaf(a, h.y, acc.y);
        r = rn; a = an;
    }
    float inv = g_inv2[n];
    float2 bv = ((const float2*)b2)[lane];
    float2 o;   // h2a columns [2*lane, 2*lane+1]
    o.x = elu1(acc.x * inv + bv.x);
    o.y = elu1(acc.y * inv + bv.y);

    // edge-head factors: u = h2a·We[0:64], v = h2a·We[64:128]
    float2 we0 = ((const float2*)We)[lane];
    float2 we1 = ((const float2*)(We + 64))[lane];
    float up = o.x * we0.x + o.y * we0.y;
    float vp = o.x * we1.x + o.y * we1.y;
#pragma unroll
    for (int off = 16; off; off >>= 1) {
        up += __shfl_xor_sync(0xffffffffu, up, off);
        vp += __shfl_xor_sync(0xffffffffu, vp, off);
    }
    if (lane == 0) { g_u[n] = up; g_v[n] = vp; }

    // node output: out[n,:] = h2a @ Wn + bn (lane = output column)
    float accn = bn[lane];
#pragma unroll
    for (int kk = 0; kk < 32; kk++) {
        float hx = __shfl_sync(0xffffffffu, o.x, kk);
        float hy = __shfl_sync(0xffffffffu, o.y, kk);
        accn = fmaf(hx, Wn[(2 * kk) * 32 + lane], accn);
        accn = fmaf(hy, Wn[(2 * kk + 1) * 32 + lane], accn);
    }
    out[n * 32 + lane] = accn;
}

// ---------------- edge output (thread per edge) ----------------
__global__ void k_edgeout(const int* __restrict__ ei, const float* __restrict__ ea,
                          const float* __restrict__ We, const float* __restrict__ be,
                          float* __restrict__ out) {
    int e = blockIdx.x * blockDim.x + threadIdx.x;
    if (e >= NE) return;
    int r = ei[e], c = ei[NE + e];
    float t = g_u[r] + g_v[c] + be[0];
    const float4* eav = (const float4*)(ea + (size_t)e * 16);
    const float4* wev = (const float4*)(We + 128);
    float4 w0 = wev[0], w1 = wev[1], w2 = wev[2], w3 = wev[3];
    float4 e0 = eav[0], e1 = eav[1], e2 = eav[2], e3 = eav[3];
    t += e0.x * w0.x + e0.y * w0.y + e0.z * w0.z + e0.w * w0.w;
    t += e1.x * w1.x + e1.y * w1.y + e1.z * w1.z + e1.w * w1.w;
    t += e2.x * w2.x + e2.y * w2.y + e2.z * w2.z + e2.w * w2.w;
    t += e3.x * w3.x + e3.y * w3.y + e3.z * w3.z + e3.w * w3.w;
    out[NN * 32 + e] = t;
}

// ---------------- launch ----------------
extern "C" void kernel_launch(void* const* d_in, const int* in_sizes, int n_in,
                              void* d_out, int out_size) {
    const float* x   = (const float*)d_in[0];
    const int*   ei  = (const int*)  d_in[1];
    const float* ea  = (const float*)d_in[2];
    const float* W1  = (const float*)d_in[3];
    const float* a1s = (const float*)d_in[4];
    const float* a1d = (const float*)d_in[5];
    const float* b1  = (const float*)d_in[6];
    const float* W2  = (const float*)d_in[7];
    const float* a2s = (const float*)d_in[8];
    const float* a2d = (const float*)d_in[9];
    const float* b2  = (const float*)d_in[10];
    const float* Wn  = (const float*)d_in[11];
    const float* bn  = (const float*)d_in[12];
    const float* We  = (const float*)d_in[13];
    const float* be  = (const float*)d_in[14];
    float* out = (float*)d_out;

    // CSR build (by destination), includes self-loops
    k_deg_init<<<(NN + 255) / 256, 256>>>();
    k_hist   <<<(NE + 255) / 256, 256>>>(ei + NE);
    k_scanA  <<<NB, 256>>>();
    k_scanB  <<<1, 256>>>();
    k_scanC  <<<NB, 256>>>();
    k_scatter<<<(NT + 255) / 256, 256>>>(ei);

    // Layer 1
    k_prew <<<1, 512>>>(W1, a1s, a1d);
    k_al1x <<<(NN + 7) / 8, 256>>>(x);
    k_gemm1<<<(NN + 31) / 32, 256>>>(x, W1);
    k_msz1 <<<(NN * 32 + 255) / 256, 256>>>();
    k_agg1 <<<(NN * 32 + 255) / 256, 256>>>(b1);

    // Layer 2
    k_gemm2<<<(NN + 15) / 16, 256>>>(W2);
    k_al2  <<<(NN * 32 + 255) / 256, 256>>>(a2s, a2d);
    k_msz2 <<<(NN * 32 + 255) / 256, 256>>>();
    k_agg2out<<<(NN * 32 + 255) / 256, 256>>>(b2, Wn, bn, We, out);

    // Outputs
    k_edgeout<<<(NE + 255) / 256, 256>>>(ei, ea, We, be, out);
}

// round 4
// speedup vs baseline: 1.6284x; 1.0932x over previous
#include <cuda_runtime.h>
#include <cuda_fp16.h>
#include <math.h>

#define NN 50000
#define NE 800000
#define NT (NE + NN)
#define NB 196   // 196*256 = 50176 >= NN

// ---------------- scratch (static __device__, allocation-free) ----------------
__device__ __half g_h1h[NN * 256];   // layer1 pre-agg features (fp16)
__device__ float  g_h1a[NN * 256];   // layer1 output (post agg + b1 + elu)
__device__ float  g_wt1[8 * 64];     // folded W1@a1 (4 src heads, 4 dst heads)
__device__ float  g_al1s[NN * 4];
__device__ float  g_al1d[NN * 4];
__device__ float  g_h2 [NN * 64];    // layer2 pre-agg features
__device__ float  g_al2s[NN];
__device__ float  g_al2d[NN];
__device__ float  g_u[NN];           // dot(h2a[n], We[0:64])
__device__ float  g_v[NN];           // dot(h2a[n], We[64:128])
__device__ int    g_deg[NN];
__device__ int    g_off[NN + 1];
__device__ int    g_cur[NN];
__device__ int    g_bsum[NB];
__device__ int    g_bbase[NB];
__device__ int    g_row[NT];         // CSR (by destination): source node per slot

__device__ __forceinline__ float lrelu(float v) { return v > 0.f ? v : 0.2f * v; }
__device__ __forceinline__ float elu1(float v)  { return v > 0.f ? v : expm1f(v); }

// packed 2xfp32 FMA (sm_103a f32x2 pipe; 2x FFMA throughput)
__device__ __forceinline__ float2 ffma2(float2 a, float2 b, float2 c) {
    float2 d;
    asm("fma.rn.f32x2 %0, %1, %2, %3;"
        : "=l"(reinterpret_cast<unsigned long long&>(d))
        : "l"(reinterpret_cast<unsigned long long&>(a)),
          "l"(reinterpret_cast<unsigned long long&>(b)),
          "l"(reinterpret_cast<unsigned long long&>(c)));
    return d;
}

// ---------------- CSR build ----------------
__global__ void k_deg_init() {
    int i = blockIdx.x * blockDim.x + threadIdx.x;
    if (i < NN) g_deg[i] = 1;  // self-loop
}

__global__ void k_hist(const int* __restrict__ col) {
    int e = blockIdx.x * blockDim.x + threadIdx.x;
    if (e < NE) atomicAdd(&g_deg[col[e]], 1);
}

__global__ void k_scanA() {  // grid NB, block 256: per-block exclusive scan
    __shared__ int ss[256];
    int b = blockIdx.x, t = threadIdx.x, i = b * 256 + t;
    int d = (i < NN) ? g_deg[i] : 0;
    ss[t] = d; __syncthreads();
    for (int o = 1; o < 256; o <<= 1) {
        int v = 0; if (t >= o) v = ss[t - o];
        __syncthreads();
        if (t >= o) ss[t] += v;
        __syncthreads();
    }
    if (i < NN) g_off[i] = ss[t] - d;
    if (t == 255) g_bsum[b] = ss[255];
}

__global__ void k_scanB() {  // 1 block 256: scan of block sums
    __shared__ int ss[256];
    int t = threadIdx.x;
    int v = (t < NB) ? g_bsum[t] : 0;
    ss[t] = v; __syncthreads();
    for (int o = 1; o < 256; o <<= 1) {
        int u = 0; if (t >= o) u = ss[t - o];
        __syncthreads();
        if (t >= o) ss[t] += u;
        __syncthreads();
    }
    if (t < NB) g_bbase[t] = ss[t] - v;
    if (t == NB - 1) g_off[NN] = ss[t];
}

__global__ void k_scanC() {  // grid NB: add block bases
    int b = blockIdx.x, i = b * 256 + threadIdx.x;
    if (i < NN) {
        int v = g_off[i] + g_bbase[b];
        g_off[i] = v; g_cur[i] = v;
    }
}

__global__ void k_scatter(const int* __restrict__ ei) {
    int e = blockIdx.x * blockDim.x + threadIdx.x;
    if (e >= NT) return;
    int r, c;
    if (e < NE) { r = ei[e]; c = ei[NE + e]; } else { r = c = e - NE; }
    int pos = atomicAdd(&g_cur[c], 1);
    g_row[pos] = r;
}

// ---------------- folded attention weights: wt1[o][k] = sum_c W1[k, h*64+c]*a[h][c] --
__global__ void k_prew(const float* __restrict__ W1, const float* __restrict__ a1s,
                       const float* __restrict__ a1d) {
    int t = threadIdx.x;   // 512 threads, 1 block
    if (t >= 512) return;
    int o = t >> 6, k = t & 63;
    int hh = o & 3;
    const float* a = (o < 4) ? a1s : a1d;
    float s = 0.f;
#pragma unroll 8
    for (int c = 0; c < 64; c++) s += W1[k * 256 + hh * 64 + c] * a[hh * 64 + c];
    g_wt1[o * 64 + k] = s;
}

// ---------------- layer-1 attention logits directly from x (warp per node) --------
__global__ __launch_bounds__(256) void k_al1x(const float* __restrict__ x) {
    __shared__ float ws[8][64];
    int tid = threadIdx.x;
    for (int i = tid; i < 512; i += 256) ws[i >> 6][i & 63] = g_wt1[i];
    __syncthreads();
    int n = blockIdx.x * 8 + (tid >> 5);
    int lane = tid & 31;
    if (n >= NN) return;
    float xv0 = x[n * 64 + lane], xv1 = x[n * 64 + 32 + lane];
    float p[8];
#pragma unroll
    for (int o = 0; o < 8; o++) p[o] = xv0 * ws[o][lane] + xv1 * ws[o][32 + lane];
#pragma unroll
    for (int off = 16; off; off >>= 1)
#pragma unroll
        for (int o = 0; o < 8; o++) p[o] += __shfl_xor_sync(0xffffffffu, p[o], off);
    if (lane == 0) {
        *(float4*)&g_al1s[n * 4] = make_float4(p[0], p[1], p[2], p[3]);
        *(float4*)&g_al1d[n * 4] = make_float4(p[4], p[5], p[6], p[7]);
    }
}

// ---------------- GEMM1: h1 = x[N,64] @ W1[64,256], store fp16, f32x2 FMA ----------
__global__ __launch_bounds__(256) void k_gemm1(const float* __restrict__ x,
                                               const float* __restrict__ W1) {
    __shared__ float2 xs[32][32];    // 32 rows x 32 k-pairs (flat == row-major 64 floats)
    int col = threadIdx.x;           // 0..255
    int row0 = blockIdx.x * 32;
    float2 w2[32];
#pragma unroll
    for (int k2 = 0; k2 < 32; k2++)
        w2[k2] = make_float2(W1[(2 * k2) * 256 + col], W1[(2 * k2 + 1) * 256 + col]);
    int nrows = NN - row0; if (nrows > 32) nrows = 32;
    for (int i = col; i < nrows * 64; i += 256)
        ((float*)xs)[i] = x[row0 * 64 + i];
    __syncthreads();
    for (int r = 0; r < nrows; r++) {
        float2 acc2 = {0.f, 0.f};
#pragma unroll
        for (int k2 = 0; k2 < 32; k2++) acc2 = ffma2(xs[r][k2], w2[k2], acc2);
        g_h1h[(size_t)(row0 + r) * 256 + col] = __float2half_rn(acc2.x + acc2.y);
    }
}

// ------- layer-1 fused softmax + aggregation (warp per dst node, fp16 rows) -------
__global__ void k_agg1(const float* __restrict__ b1) {
    int n    = (blockIdx.x * blockDim.x + threadIdx.x) >> 5;
    int lane = threadIdx.x & 31;
    if (n >= NN) return;
    int s0 = g_off[n], s1 = g_off[n + 1];
    int h = lane >> 3;  // this lane's 8 columns [lane*8, lane*8+8) all in head h
    float ad = g_al1d[n * 4 + h];

    float2 acc[4] = {{0,0},{0,0},{0,0},{0,0}};
    float z = 0.f;
    int   r  = g_row[s0];            // degree >= 1 always (self-loop)
    float al = g_al1s[r * 4 + h];
    for (int i = s0; i < s1; i++) {
        int rn = r; float aln = al;
        if (i + 1 < s1) { rn = g_row[i + 1]; aln = g_al1s[rn * 4 + h]; }
        float e = __expf(lrelu(al + ad));
        z += e;
        float4 raw = ((const float4*)(g_h1h + (size_t)r * 256))[lane];
        const __half2* hp = (const __half2*)&raw;
        float2 ev = make_float2(e, e);
#pragma unroll
        for (int j = 0; j < 4; j++)
            acc[j] = ffma2(ev, __half22float2(hp[j]), acc[j]);
        r = rn; al = aln;
    }
    float inv = 1.f / (z + 1e-16f);
    float4 bv0 = *(const float4*)(b1 + lane * 8);
    float4 bv1 = *(const float4*)(b1 + lane * 8 + 4);
    float4 o0, o1;
    o0.x = elu1(acc[0].x * inv + bv0.x); o0.y = elu1(acc[0].y * inv + bv0.y);
    o0.z = elu1(acc[1].x * inv + bv0.z); o0.w = elu1(acc[1].y * inv + bv0.w);
    o1.x = elu1(acc[2].x * inv + bv1.x); o1.y = elu1(acc[2].y * inv + bv1.y);
    o1.z = elu1(acc[3].x * inv + bv1.z); o1.w = elu1(acc[3].y * inv + bv1.w);
    float4* dst = (float4*)(g_h1a + (size_t)n * 256 + lane * 8);
    dst[0] = o0;
    dst[1] = o1;
}

// ------- GEMM2: h2 = h1a[N,256] @ W2[256,64], fused layer-2 logits (al2) ----------
__global__ __launch_bounds__(256) void k_gemm2(const float* __restrict__ W2,
                                               const float* __restrict__ a2s,
                                               const float* __restrict__ a2d) {
    __shared__ float2 xs[16][128];   // flat == row-major 256 floats
    __shared__ float  red[4][16][64];
    __shared__ float  sps[16], spd[16];
    int tid = threadIdx.x;
    int j = tid & 63, q = tid >> 6;  // q: K-quarter
    int row0 = blockIdx.x * 16;
    int nrows = NN - row0; if (nrows > 16) nrows = 16;
    float2 w2[32];
#pragma unroll
    for (int k2 = 0; k2 < 32; k2++)
        w2[k2] = make_float2(W2[(q * 64 + 2 * k2) * 64 + j], W2[(q * 64 + 2 * k2 + 1) * 64 + j]);
    if (tid < 16) { sps[tid] = 0.f; spd[tid] = 0.f; }
    for (int i = tid; i < nrows * 256; i += 256)
        ((float*)xs)[i] = g_h1a[row0 * 256 + i];
    __syncthreads();
    for (int r = 0; r < nrows; r++) {
        float2 acc2 = {0.f, 0.f};
#pragma unroll
        for (int k2 = 0; k2 < 32; k2++) acc2 = ffma2(xs[r][q * 32 + k2], w2[k2], acc2);
        red[q][r][j] = acc2.x + acc2.y;
    }
    __syncthreads();
    for (int i = tid; i < nrows * 64; i += 256) {
        int r = i >> 6, jj = i & 63;
        float v = red[0][r][jj] + red[1][r][jj] + red[2][r][jj] + red[3][r][jj];
        g_h2[row0 * 64 + i] = v;
        float ps = v * a2s[jj], pd = v * a2d[jj];
#pragma unroll
        for (int off = 16; off; off >>= 1) {
            ps += __shfl_xor_sync(0xffffffffu, ps, off);
            pd += __shfl_xor_sync(0xffffffffu, pd, off);
        }
        if ((tid & 31) == 0) { atomicAdd(&sps[r], ps); atomicAdd(&spd[r], pd); }
    }
    __syncthreads();
    if (tid < nrows) {
        g_al2s[row0 + tid] = sps[tid];
        g_al2d[row0 + tid] = spd[tid];
    }
}

// --- layer-2 fused softmax + aggregation + node output + edge factors (warp/node) -
__global__ void k_agg2out(const float* __restrict__ b2, const float* __restrict__ Wn,
                          const float* __restrict__ bn, const float* __restrict__ We,
                          float* __restrict__ out) {
    int n    = (blockIdx.x * blockDim.x + threadIdx.x) >> 5;
    int lane = threadIdx.x & 31;
    if (n >= NN) return;
    int s0 = g_off[n], s1 = g_off[n + 1];
    float ad = g_al2d[n];

    float2 acc = {0.f, 0.f};
    float z = 0.f;
    int   r  = g_row[s0];
    float al = g_al2s[r];
    for (int i = s0; i < s1; i++) {
        int rn = r; float aln = al;
        if (i + 1 < s1) { rn = g_row[i + 1]; aln = g_al2s[rn]; }
        float e = __expf(lrelu(al + ad));
        z += e;
        float2 h = ((const float2*)(g_h2 + (size_t)r * 64))[lane];
        acc = ffma2(make_float2(e, e), h, acc);
        r = rn; al = aln;
    }
    float inv = 1.f / (z + 1e-16f);
    float2 bv = ((const float2*)b2)[lane];
    float2 o;   // h2a columns [2*lane, 2*lane+1]
    o.x = elu1(acc.x * inv + bv.x);
    o.y = elu1(acc.y * inv + bv.y);

    // edge-head factors: u = h2a·We[0:64], v = h2a·We[64:128]
    float2 we0 = ((const float2*)We)[lane];
    float2 we1 = ((const float2*)(We + 64))[lane];
    float up = o.x * we0.x + o.y * we0.y;
    float vp = o.x * we1.x + o.y * we1.y;
#pragma unroll
    for (int off = 16; off; off >>= 1) {
        up += __shfl_xor_sync(0xffffffffu, up, off);
        vp += __shfl_xor_sync(0xffffffffu, vp, off);
    }
    if (lane == 0) { g_u[n] = up; g_v[n] = vp; }

    // node output: out[n,:] = h2a @ Wn + bn (lane = output column)
    float accn = bn[lane];
#pragma unroll
    for (int kk = 0; kk < 32; kk++) {
        float hx = __shfl_sync(0xffffffffu, o.x, kk);
        float hy = __shfl_sync(0xffffffffu, o.y, kk);
        accn = fmaf(hx, Wn[(2 * kk) * 32 + lane], accn);
        accn = fmaf(hy, Wn[(2 * kk + 1) * 32 + lane], accn);
    }
    out[n * 32 + lane] = accn;
}

// ---------------- edge output (thread per edge) ----------------
__global__ void k_edgeout(const int* __restrict__ ei, const float* __restrict__ ea,
                          const float* __restrict__ We, const float* __restrict__ be,
                          float* __restrict__ out) {
    int e = blockIdx.x * blockDim.x + threadIdx.x;
    if (e >= NE) return;
    int r = ei[e], c = ei[NE + e];
    float t = g_u[r] + g_v[c] + be[0];
    const float4* eav = (const float4*)(ea + (size_t)e * 16);
    const float4* wev = (const float4*)(We + 128);
    float4 w0 = wev[0], w1 = wev[1], w2 = wev[2], w3 = wev[3];
    float4 e0 = eav[0], e1 = eav[1], e2 = eav[2], e3 = eav[3];
    t += e0.x * w0.x + e0.y * w0.y + e0.z * w0.z + e0.w * w0.w;
    t += e1.x * w1.x + e1.y * w1.y + e1.z * w1.z + e1.w * w1.w;
    t += e2.x * w2.x + e2.y * w2.y + e2.z * w2.z + e2.w * w2.w;
    t += e3.x * w3.x + e3.y * w3.y + e3.z * w3.z + e3.w * w3.w;
    out[NN * 32 + e] = t;
}

// ---------------- launch ----------------
extern "C" void kernel_launch(void* const* d_in, const int* in_sizes, int n_in,
                              void* d_out, int out_size) {
    const float* x   = (const float*)d_in[0];
    const int*   ei  = (const int*)  d_in[1];
    const float* ea  = (const float*)d_in[2];
    const float* W1  = (const float*)d_in[3];
    const float* a1s = (const float*)d_in[4];
    const float* a1d = (const float*)d_in[5];
    const float* b1  = (const float*)d_in[6];
    const float* W2  = (const float*)d_in[7];
    const float* a2s = (const float*)d_in[8];
    const float* a2d = (const float*)d_in[9];
    const float* b2  = (const float*)d_in[10];
    const float* Wn  = (const float*)d_in[11];
    const float* bn  = (const float*)d_in[12];
    const float* We  = (const float*)d_in[13];
    const float* be  = (const float*)d_in[14];
    float* out = (float*)d_out;

    // CSR build (by destination), includes self-loops
    k_deg_init<<<(NN + 255) / 256, 256>>>();
    k_hist   <<<(NE + 255) / 256, 256>>>(ei + NE);
    k_scanA  <<<NB, 256>>>();
    k_scanB  <<<1, 256>>>();
    k_scanC  <<<NB, 256>>>();
    k_scatter<<<(NT + 255) / 256, 256>>>(ei);

    // Layer 1
    k_prew <<<1, 512>>>(W1, a1s, a1d);
    k_al1x <<<(NN + 7) / 8, 256>>>(x);
    k_gemm1<<<(NN + 31) / 32, 256>>>(x, W1);
    k_agg1 <<<(NN * 32 + 255) / 256, 256>>>(b1);

    // Layer 2
    k_gemm2<<<(NN + 15) / 16, 256>>>(W2, a2s, a2d);
    k_agg2out<<<(NN * 32 + 255) / 256, 256>>>(b2, Wn, bn, We, out);

    // Outputs
    k_edgeout<<<(NE + 255) / 256, 256>>>(ei, ea, We, be, out);
}

// round 5
// speedup vs baseline: 1.7066x; 1.0480x over previous
#include <cuda_runtime.h>
#include <cuda_fp16.h>
#include <math.h>

#define NN 50000
#define NE 800000
#define NT (NE + NN)
#define NB 196   // 196*256 = 50176 >= NN

// ---------------- scratch (static __device__, allocation-free) ----------------
__device__ __half g_h1h[NN * 256];   // layer1 pre-agg features (fp16)
__device__ float  g_h1a[NN * 256];   // layer1 output (post agg + b1 + elu)
__device__ float  g_wt1[8 * 64];     // folded W1@a1 (4 src heads, 4 dst heads)
__device__ float  g_al1s[NN * 4];
__device__ float  g_al1d[NN * 4];
__device__ float  g_h2 [NN * 64];    // layer2 pre-agg features
__device__ float  g_al2s[NN];
__device__ float  g_al2d[NN];
__device__ float  g_u[NN];           // dot(h2a[n], We[0:64])
__device__ float  g_v[NN];           // dot(h2a[n], We[64:128])
__device__ int    g_deg[NN];
__device__ int    g_off[NN + 1];
__device__ int    g_cur[NN];
__device__ int    g_bsum[NB];
__device__ int    g_bbase[NB];
__device__ int    g_row[NT];         // CSR (by destination): source node per slot

__device__ __forceinline__ float lrelu(float v) { return v > 0.f ? v : 0.2f * v; }
__device__ __forceinline__ float elu1(float v)  { return v > 0.f ? v : expm1f(v); }

// packed 2xfp32 FMA (sm_103a f32x2 pipe; 2x FFMA throughput)
__device__ __forceinline__ float2 ffma2(float2 a, float2 b, float2 c) {
    float2 d;
    asm("fma.rn.f32x2 %0, %1, %2, %3;"
        : "=l"(reinterpret_cast<unsigned long long&>(d))
        : "l"(reinterpret_cast<unsigned long long&>(a)),
          "l"(reinterpret_cast<unsigned long long&>(b)),
          "l"(reinterpret_cast<unsigned long long&>(c)));
    return d;
}

// ---------------- CSR build ----------------
__global__ void k_deg_init() {
    int i = blockIdx.x * blockDim.x + threadIdx.x;
    if (i < NN) g_deg[i] = 1;  // self-loop
}

__global__ void k_hist(const int* __restrict__ col) {
    int e = blockIdx.x * blockDim.x + threadIdx.x;
    if (e < NE) atomicAdd(&g_deg[col[e]], 1);
}

__global__ void k_scanA() {  // grid NB, block 256: per-block exclusive scan
    __shared__ int ss[256];
    int b = blockIdx.x, t = threadIdx.x, i = b * 256 + t;
    int d = (i < NN) ? g_deg[i] : 0;
    ss[t] = d; __syncthreads();
    for (int o = 1; o < 256; o <<= 1) {
        int v = 0; if (t >= o) v = ss[t - o];
        __syncthreads();
        if (t >= o) ss[t] += v;
        __syncthreads();
    }
    if (i < NN) g_off[i] = ss[t] - d;
    if (t == 255) g_bsum[b] = ss[255];
}

__global__ void k_scanB() {  // 1 block 256: scan of block sums
    __shared__ int ss[256];
    int t = threadIdx.x;
    int v = (t < NB) ? g_bsum[t] : 0;
    ss[t] = v; __syncthreads();
    for (int o = 1; o < 256; o <<= 1) {
        int u = 0; if (t >= o) u = ss[t - o];
        __syncthreads();
        if (t >= o) ss[t] += u;
        __syncthreads();
    }
    if (t < NB) g_bbase[t] = ss[t] - v;
    if (t == NB - 1) g_off[NN] = ss[t];
}

__global__ void k_scanC() {  // grid NB: add block bases
    int b = blockIdx.x, i = b * 256 + threadIdx.x;
    if (i < NN) {
        int v = g_off[i] + g_bbase[b];
        g_off[i] = v; g_cur[i] = v;
    }
}

__global__ void k_scatter(const int* __restrict__ ei) {
    int e = blockIdx.x * blockDim.x + threadIdx.x;
    if (e >= NT) return;
    int r, c;
    if (e < NE) { r = ei[e]; c = ei[NE + e]; } else { r = c = e - NE; }
    int pos = atomicAdd(&g_cur[c], 1);
    g_row[pos] = r;
}

// ---------------- folded attention weights: wt1[o][k] = sum_c W1[k, h*64+c]*a[h][c] --
__global__ void k_prew(const float* __restrict__ W1, const float* __restrict__ a1s,
                       const float* __restrict__ a1d) {
    int t = threadIdx.x;   // 512 threads, 1 block
    if (t >= 512) return;
    int o = t >> 6, k = t & 63;
    int hh = o & 3;
    const float* a = (o < 4) ? a1s : a1d;
    float s = 0.f;
#pragma unroll 8
    for (int c = 0; c < 64; c++) s += W1[k * 256 + hh * 64 + c] * a[hh * 64 + c];
    g_wt1[o * 64 + k] = s;
}

// ---------------- layer-1 attention logits directly from x (warp per node) --------
__global__ __launch_bounds__(256) void k_al1x(const float* __restrict__ x) {
    __shared__ float ws[8][64];
    int tid = threadIdx.x;
    for (int i = tid; i < 512; i += 256) ws[i >> 6][i & 63] = g_wt1[i];
    __syncthreads();
    int n = blockIdx.x * 8 + (tid >> 5);
    int lane = tid & 31;
    if (n >= NN) return;
    float xv0 = x[n * 64 + lane], xv1 = x[n * 64 + 32 + lane];
    float p[8];
#pragma unroll
    for (int o = 0; o < 8; o++) p[o] = xv0 * ws[o][lane] + xv1 * ws[o][32 + lane];
#pragma unroll
    for (int off = 16; off; off >>= 1)
#pragma unroll
        for (int o = 0; o < 8; o++) p[o] += __shfl_xor_sync(0xffffffffu, p[o], off);
    if (lane == 0) {
        *(float4*)&g_al1s[n * 4] = make_float4(p[0], p[1], p[2], p[3]);
        *(float4*)&g_al1d[n * 4] = make_float4(p[4], p[5], p[6], p[7]);
    }
}

// ---------------- GEMM1: h1 = x[N,64] @ W1[64,256], store fp16, f32x2 FMA ----------
__global__ __launch_bounds__(256) void k_gemm1(const float* __restrict__ x,
                                               const float* __restrict__ W1) {
    __shared__ float2 xs[32][32];    // 32 rows x 32 k-pairs (flat == row-major 64 floats)
    int col = threadIdx.x;           // 0..255
    int row0 = blockIdx.x * 32;
    float2 w2[32];
#pragma unroll
    for (int k2 = 0; k2 < 32; k2++)
        w2[k2] = make_float2(W1[(2 * k2) * 256 + col], W1[(2 * k2 + 1) * 256 + col]);
    int nrows = NN - row0; if (nrows > 32) nrows = 32;
    for (int i = col; i < nrows * 64; i += 256)
        ((float*)xs)[i] = x[row0 * 64 + i];
    __syncthreads();
    for (int r = 0; r < nrows; r++) {
        float2 acc2 = {0.f, 0.f};
#pragma unroll
        for (int k2 = 0; k2 < 32; k2++) acc2 = ffma2(xs[r][k2], w2[k2], acc2);
        g_h1h[(size_t)(row0 + r) * 256 + col] = __float2half_rn(acc2.x + acc2.y);
    }
}

// ------- layer-1 fused softmax + aggregation (warp per dst node, fp16 rows) -------
__global__ void k_agg1(const float* __restrict__ b1) {
    int n    = (blockIdx.x * blockDim.x + threadIdx.x) >> 5;
    int lane = threadIdx.x & 31;
    if (n >= NN) return;
    int s0 = g_off[n], s1 = g_off[n + 1];
    int h = lane >> 3;  // this lane's 8 columns [lane*8, lane*8+8) all in head h
    float ad = g_al1d[n * 4 + h];

    float2 acc[4] = {{0,0},{0,0},{0,0},{0,0}};
    float z = 0.f;
    int   r  = g_row[s0];            // degree >= 1 always (self-loop)
    float al = g_al1s[r * 4 + h];
    for (int i = s0; i < s1; i++) {
        int rn = r; float aln = al;
        if (i + 1 < s1) { rn = g_row[i + 1]; aln = g_al1s[rn * 4 + h]; }
        float e = __expf(lrelu(al + ad));
        z += e;
        float4 raw = ((const float4*)(g_h1h + (size_t)r * 256))[lane];
        const __half2* hp = (const __half2*)&raw;
        float2 ev = make_float2(e, e);
#pragma unroll
        for (int j = 0; j < 4; j++)
            acc[j] = ffma2(ev, __half22float2(hp[j]), acc[j]);
        r = rn; al = aln;
    }
    float inv = 1.f / (z + 1e-16f);
    float4 bv0 = *(const float4*)(b1 + lane * 8);
    float4 bv1 = *(const float4*)(b1 + lane * 8 + 4);
    float4 o0, o1;
    o0.x = elu1(acc[0].x * inv + bv0.x); o0.y = elu1(acc[0].y * inv + bv0.y);
    o0.z = elu1(acc[1].x * inv + bv0.z); o0.w = elu1(acc[1].y * inv + bv0.w);
    o1.x = elu1(acc[2].x * inv + bv1.x); o1.y = elu1(acc[2].y * inv + bv1.y);
    o1.z = elu1(acc[3].x * inv + bv1.z); o1.w = elu1(acc[3].y * inv + bv1.w);
    float4* dst = (float4*)(g_h1a + (size_t)n * 256 + lane * 8);
    dst[0] = o0;
    dst[1] = o1;
}

// ------- GEMM2: h2 = h1a[N,256] @ W2[256,64], fused layer-2 logits (al2) ----------
__global__ __launch_bounds__(256) void k_gemm2(const float* __restrict__ W2,
                                               const float* __restrict__ a2s,
                                               const float* __restrict__ a2d) {
    __shared__ float2 xs[16][128];   // flat == row-major 256 floats
    __shared__ float  red[4][16][64];
    __shared__ float  sps[16], spd[16];
    int tid = threadIdx.x;
    int j = tid & 63, q = tid >> 6;  // q: K-quarter
    int row0 = blockIdx.x * 16;
    int nrows = NN - row0; if (nrows > 16) nrows = 16;
    float2 w2[32];
#pragma unroll
    for (int k2 = 0; k2 < 32; k2++)
        w2[k2] = make_float2(W2[(q * 64 + 2 * k2) * 64 + j], W2[(q * 64 + 2 * k2 + 1) * 64 + j]);
    if (tid < 16) { sps[tid] = 0.f; spd[tid] = 0.f; }
    for (int i = tid; i < nrows * 256; i += 256)
        ((float*)xs)[i] = g_h1a[row0 * 256 + i];
    __syncthreads();
    for (int r = 0; r < nrows; r++) {
        float2 acc2 = {0.f, 0.f};
#pragma unroll
        for (int k2 = 0; k2 < 32; k2++) acc2 = ffma2(xs[r][q * 32 + k2], w2[k2], acc2);
        red[q][r][j] = acc2.x + acc2.y;
    }
    __syncthreads();
    for (int i = tid; i < nrows * 64; i += 256) {
        int r = i >> 6, jj = i & 63;
        float v = red[0][r][jj] + red[1][r][jj] + red[2][r][jj] + red[3][r][jj];
        g_h2[row0 * 64 + i] = v;
        float ps = v * a2s[jj], pd = v * a2d[jj];
#pragma unroll
        for (int off = 16; off; off >>= 1) {
            ps += __shfl_xor_sync(0xffffffffu, ps, off);
            pd += __shfl_xor_sync(0xffffffffu, pd, off);
        }
        if ((tid & 31) == 0) { atomicAdd(&sps[r], ps); atomicAdd(&spd[r], pd); }
    }
    __syncthreads();
    if (tid < nrows) {
        g_al2s[row0 + tid] = sps[tid];
        g_al2d[row0 + tid] = spd[tid];
    }
}

// --- layer-2 fused softmax + aggregation + node output + edge factors (warp/node) -
__global__ void k_agg2out(const float* __restrict__ b2, const float* __restrict__ Wn,
                          const float* __restrict__ bn, const float* __restrict__ We,
                          float* __restrict__ out) {
    int n    = (blockIdx.x * blockDim.x + threadIdx.x) >> 5;
    int lane = threadIdx.x & 31;
    if (n >= NN) return;
    int s0 = g_off[n], s1 = g_off[n + 1];
    float ad = g_al2d[n];

    float2 acc = {0.f, 0.f};
    float z = 0.f;
    int   r  = g_row[s0];
    float al = g_al2s[r];
    for (int i = s0; i < s1; i++) {
        int rn = r; float aln = al;
        if (i + 1 < s1) { rn = g_row[i + 1]; aln = g_al2s[rn]; }
        float e = __expf(lrelu(al + ad));
        z += e;
        float2 h = ((const float2*)(g_h2 + (size_t)r * 64))[lane];
        acc = ffma2(make_float2(e, e), h, acc);
        r = rn; al = aln;
    }
    float inv = 1.f / (z + 1e-16f);
    float2 bv = ((const float2*)b2)[lane];
    float2 o;   // h2a columns [2*lane, 2*lane+1]
    o.x = elu1(acc.x * inv + bv.x);
    o.y = elu1(acc.y * inv + bv.y);

    // edge-head factors: u = h2a·We[0:64], v = h2a·We[64:128]
    float2 we0 = ((const float2*)We)[lane];
    float2 we1 = ((const float2*)(We + 64))[lane];
    float up = o.x * we0.x + o.y * we0.y;
    float vp = o.x * we1.x + o.y * we1.y;
#pragma unroll
    for (int off = 16; off; off >>= 1) {
        up += __shfl_xor_sync(0xffffffffu, up, off);
        vp += __shfl_xor_sync(0xffffffffu, vp, off);
    }
    if (lane == 0) { g_u[n] = up; g_v[n] = vp; }

    // node output: out[n,:] = h2a @ Wn + bn (lane = output column)
    float accn = bn[lane];
#pragma unroll
    for (int kk = 0; kk < 32; kk++) {
        float hx = __shfl_sync(0xffffffffu, o.x, kk);
        float hy = __shfl_sync(0xffffffffu, o.y, kk);
        accn = fmaf(hx, Wn[(2 * kk) * 32 + lane], accn);
        accn = fmaf(hy, Wn[(2 * kk + 1) * 32 + lane], accn);
    }
    out[n * 32 + lane] = accn;
}

// ------- edge output part A: edge_attr contribution (overlappable) -------
__global__ void k_edgeA(const float* __restrict__ ea, const float* __restrict__ We,
                        const float* __restrict__ be, float* __restrict__ out) {
    int e = blockIdx.x * blockDim.x + threadIdx.x;
    if (e >= NE) return;
    const float4* eav = (const float4*)(ea + (size_t)e * 16);
    const float4* wev = (const float4*)(We + 128);
    float4 w0 = wev[0], w1 = wev[1], w2 = wev[2], w3 = wev[3];
    float4 e0 = eav[0], e1 = eav[1], e2 = eav[2], e3 = eav[3];
    float t = be[0];
    t += e0.x * w0.x + e0.y * w0.y + e0.z * w0.z + e0.w * w0.w;
    t += e1.x * w1.x + e1.y * w1.y + e1.z * w1.z + e1.w * w1.w;
    t += e2.x * w2.x + e2.y * w2.y + e2.z * w2.z + e2.w * w2.w;
    t += e3.x * w3.x + e3.y * w3.y + e3.z * w3.z + e3.w * w3.w;
    out[NN * 32 + e] = t;
}

// ------- edge output part B: add node factors (tail, small) -------
__global__ void k_edgeB(const int* __restrict__ ei, float* __restrict__ out) {
    int e = blockIdx.x * blockDim.x + threadIdx.x;
    if (e >= NE) return;
    int r = ei[e], c = ei[NE + e];
    out[NN * 32 + e] += g_u[r] + g_v[c];
}

// ---------------- launch ----------------
extern "C" void kernel_launch(void* const* d_in, const int* in_sizes, int n_in,
                              void* d_out, int out_size) {
    const float* x   = (const float*)d_in[0];
    const int*   ei  = (const int*)  d_in[1];
    const float* ea  = (const float*)d_in[2];
    const float* W1  = (const float*)d_in[3];
    const float* a1s = (const float*)d_in[4];
    const float* a1d = (const float*)d_in[5];
    const float* b1  = (const float*)d_in[6];
    const float* W2  = (const float*)d_in[7];
    const float* a2s = (const float*)d_in[8];
    const float* a2d = (const float*)d_in[9];
    const float* b2  = (const float*)d_in[10];
    const float* Wn  = (const float*)d_in[11];
    const float* bn  = (const float*)d_in[12];
    const float* We  = (const float*)d_in[13];
    const float* be  = (const float*)d_in[14];
    float* out = (float*)d_out;

    // one-time side stream + events (resources only; no device memory)
    static cudaStream_t s2 = [] {
        cudaStream_t s; cudaStreamCreateWithFlags(&s, cudaStreamNonBlocking); return s;
    }();
    static cudaEvent_t evFork = [] {
        cudaEvent_t e; cudaEventCreateWithFlags(&e, cudaEventDisableTiming); return e;
    }();
    static cudaEvent_t evJoin = [] {
        cudaEvent_t e; cudaEventCreateWithFlags(&e, cudaEventDisableTiming); return e;
    }();

    cudaStream_t s0 = 0;  // legacy default; the harness captures on it

    // fork
    cudaEventRecord(evFork, s0);
    cudaStreamWaitEvent(s2, evFork, 0);

    // branch 1 (capture stream): CSR build (by destination), includes self-loops
    k_deg_init<<<(NN + 255) / 256, 256, 0, s0>>>();
    k_hist   <<<(NE + 255) / 256, 256, 0, s0>>>(ei + NE);
    k_scanA  <<<NB, 256, 0, s0>>>();
    k_scanB  <<<1, 256, 0, s0>>>();
    k_scanC  <<<NB, 256, 0, s0>>>();
    k_scatter<<<(NT + 255) / 256, 256, 0, s0>>>(ei);

    // branch 2 (side stream): dense layer-1 work + edge_attr partial
    k_prew <<<1, 512, 0, s2>>>(W1, a1s, a1d);
    k_al1x <<<(NN + 7) / 8, 256, 0, s2>>>(x);
    k_gemm1<<<(NN + 31) / 32, 256, 0, s2>>>(x, W1);
    k_edgeA<<<(NE + 255) / 256, 256, 0, s2>>>(ea, We, be, out);
    cudaEventRecord(evJoin, s2);

    // join
    cudaStreamWaitEvent(s0, evJoin, 0);

    // tail (needs CSR + gemm1 + al1x)
    k_agg1   <<<(NN * 32 + 255) / 256, 256, 0, s0>>>(b1);
    k_gemm2  <<<(NN + 15) / 16, 256, 0, s0>>>(W2, a2s, a2d);
    k_agg2out<<<(NN * 32 + 255) / 256, 256, 0, s0>>>(b2, Wn, bn, We, out);
    k_edgeB  <<<(NE + 255) / 256, 256, 0, s0>>>(ei, out);
}

// round 6
// speedup vs baseline: 1.7672x; 1.0355x over previous
#include <cuda_runtime.h>
#include <cuda_fp16.h>
#include <math.h>

#define NN 50000
#define NE 800000
#define NT (NE + NN)
#define NB 196   // 196*256 = 50176 >= NN

// ---------------- scratch (static __device__, allocation-free) ----------------
__device__ __half g_h1h[NN * 256];   // layer1 pre-agg features (fp16)
__device__ float  g_h1a[NN * 256];   // layer1 output (post agg + b1 + elu)
__device__ float  g_wt1[8 * 64];     // folded W1@a1 (4 src heads, 4 dst heads)
__device__ float  g_al1s[NN * 4];
__device__ float  g_al1d[NN * 4];
__device__ float  g_h2 [NN * 64];    // layer2 pre-agg features
__device__ float  g_al2s[NN];
__device__ float  g_al2d[NN];
__device__ float  g_u[NN];           // dot(h2a[n], We[0:64])
__device__ float  g_v[NN];           // dot(h2a[n], We[64:128])
__device__ int    g_deg[NN];
__device__ int    g_off[NN + 1];
__device__ int    g_cur[NN];
__device__ int    g_bsum[NB];
__device__ int    g_bbase[NB];
__device__ int    g_row[NT];         // CSR (by destination): source node per slot

__device__ __forceinline__ float lrelu(float v) { return v > 0.f ? v : 0.2f * v; }
__device__ __forceinline__ float elu1(float v)  { return v > 0.f ? v : expm1f(v); }

// packed 2xfp32 FMA (sm_103a f32x2 pipe; 2x FFMA throughput)
__device__ __forceinline__ float2 ffma2(float2 a, float2 b, float2 c) {
    float2 d;
    asm("fma.rn.f32x2 %0, %1, %2, %3;"
        : "=l"(reinterpret_cast<unsigned long long&>(d))
        : "l"(reinterpret_cast<unsigned long long&>(a)),
          "l"(reinterpret_cast<unsigned long long&>(b)),
          "l"(reinterpret_cast<unsigned long long&>(c)));
    return d;
}

// ---------------- CSR build ----------------
__global__ void k_deg_init() {
    int i = blockIdx.x * blockDim.x + threadIdx.x;
    if (i < NN) g_deg[i] = 1;  // self-loop
}

__global__ void k_hist(const int* __restrict__ col) {
    int e = blockIdx.x * blockDim.x + threadIdx.x;
    if (e < NE) atomicAdd(&g_deg[col[e]], 1);
}

__global__ void k_scanA() {  // grid NB, block 256: per-block exclusive scan
    __shared__ int ss[256];
    int b = blockIdx.x, t = threadIdx.x, i = b * 256 + t;
    int d = (i < NN) ? g_deg[i] : 0;
    ss[t] = d; __syncthreads();
    for (int o = 1; o < 256; o <<= 1) {
        int v = 0; if (t >= o) v = ss[t - o];
        __syncthreads();
        if (t >= o) ss[t] += v;
        __syncthreads();
    }
    if (i < NN) g_off[i] = ss[t] - d;
    if (t == 255) g_bsum[b] = ss[255];
}

__global__ void k_scanB() {  // 1 block 256: scan of block sums
    __shared__ int ss[256];
    int t = threadIdx.x;
    int v = (t < NB) ? g_bsum[t] : 0;
    ss[t] = v; __syncthreads();
    for (int o = 1; o < 256; o <<= 1) {
        int u = 0; if (t >= o) u = ss[t - o];
        __syncthreads();
        if (t >= o) ss[t] += u;
        __syncthreads();
    }
    if (t < NB) g_bbase[t] = ss[t] - v;
    if (t == NB - 1) g_off[NN] = ss[t];
}

__global__ void k_scanC() {  // grid NB: add block bases
    int b = blockIdx.x, i = b * 256 + threadIdx.x;
    if (i < NN) {
        int v = g_off[i] + g_bbase[b];
        g_off[i] = v; g_cur[i] = v;
    }
}

__global__ void k_scatter(const int* __restrict__ ei) {
    int e = blockIdx.x * blockDim.x + threadIdx.x;
    if (e >= NT) return;
    int r, c;
    if (e < NE) { r = ei[e]; c = ei[NE + e]; } else { r = c = e - NE; }
    int pos = atomicAdd(&g_cur[c], 1);
    g_row[pos] = r;
}

// ---------------- folded attention weights: wt1[o][k] = sum_c W1[k, h*64+c]*a[h][c] --
__global__ void k_prew(const float* __restrict__ W1, const float* __restrict__ a1s,
                       const float* __restrict__ a1d) {
    int t = threadIdx.x;   // 512 threads, 1 block
    if (t >= 512) return;
    int o = t >> 6, k = t & 63;
    int hh = o & 3;
    const float* a = (o < 4) ? a1s : a1d;
    float s = 0.f;
#pragma unroll 8
    for (int c = 0; c < 64; c++) s += W1[k * 256 + hh * 64 + c] * a[hh * 64 + c];
    g_wt1[o * 64 + k] = s;
}

// --- GEMM1: h1 = x[N,64] @ W1[64,256] (fp16 out) + fused layer-1 logits ---------
__global__ __launch_bounds__(256) void k_gemm1(const float* __restrict__ x,
                                               const float* __restrict__ W1) {
    __shared__ float2 xs[32][32];    // flat == row-major 64 floats per row
    __shared__ float  ws[8][65];     // folded weights, padded (bank-conflict-free)
    int tid = threadIdx.x;           // 0..255
    int col = tid;
    int row0 = blockIdx.x * 32;
    float2 w2[32];
#pragma unroll
    for (int k2 = 0; k2 < 32; k2++)
        w2[k2] = make_float2(W1[(2 * k2) * 256 + col], W1[(2 * k2 + 1) * 256 + col]);
    for (int i = tid; i < 512; i += 256) ws[i >> 6][i & 63] = g_wt1[i];
    int nrows = NN - row0; if (nrows > 32) nrows = 32;
    for (int i = tid; i < nrows * 64; i += 256)
        ((float*)xs)[i] = x[row0 * 64 + i];
    __syncthreads();
    for (int r = 0; r < nrows; r++) {
        float2 acc2 = {0.f, 0.f};
#pragma unroll
        for (int k2 = 0; k2 < 32; k2++) acc2 = ffma2(xs[r][k2], w2[k2], acc2);
        g_h1h[(size_t)(row0 + r) * 256 + col] = __float2half_rn(acc2.x + acc2.y);
    }
    // fused al1x: thread (r = tid>>3, o = tid&7) computes dot(x[row0+r], wt1[o])
    {
        int r = tid >> 3, o = tid & 7;
        if (r < nrows) {
            const float* xr = (const float*)xs + r * 64;
            float s = 0.f;
#pragma unroll 16
            for (int k = 0; k < 64; k++) s += xr[k] * ws[o][k];
            if (o < 4) g_al1s[(row0 + r) * 4 + o] = s;
            else       g_al1d[(row0 + r) * 4 + (o - 4)] = s;
        }
    }
}

// ------- layer-1 fused softmax + aggregation (warp/node, 4-wide unroll) ----------
__global__ void k_agg1(const float* __restrict__ b1) {
    int n    = (blockIdx.x * blockDim.x + threadIdx.x) >> 5;
    int lane = threadIdx.x & 31;
    if (n >= NN) return;
    int s0 = g_off[n], s1 = g_off[n + 1];
    int h = lane >> 3;  // this lane's 8 columns [lane*8, lane*8+8) all in head h
    float ad = g_al1d[n * 4 + h];

    float2 acc[4] = {{0,0},{0,0},{0,0},{0,0}};
    float z = 0.f;
    int i = s0;
    for (; i + 4 <= s1; i += 4) {
        int r0 = g_row[i],     r1 = g_row[i + 1];
        int r2 = g_row[i + 2], r3 = g_row[i + 3];
        float al0 = g_al1s[r0 * 4 + h], al1 = g_al1s[r1 * 4 + h];
        float al2 = g_al1s[r2 * 4 + h], al3 = g_al1s[r3 * 4 + h];
        float4 w0 = ((const float4*)(g_h1h + (size_t)r0 * 256))[lane];
        float4 w1 = ((const float4*)(g_h1h + (size_t)r1 * 256))[lane];
        float4 w2 = ((const float4*)(g_h1h + (size_t)r2 * 256))[lane];
        float4 w3 = ((const float4*)(g_h1h + (size_t)r3 * 256))[lane];
        float e0 = __expf(lrelu(al0 + ad)), e1 = __expf(lrelu(al1 + ad));
        float e2 = __expf(lrelu(al2 + ad)), e3 = __expf(lrelu(al3 + ad));
        z += (e0 + e1) + (e2 + e3);
        const __half2* p0 = (const __half2*)&w0;
        const __half2* p1 = (const __half2*)&w1;
        const __half2* p2 = (const __half2*)&w2;
        const __half2* p3 = (const __half2*)&w3;
        float2 ev0 = make_float2(e0, e0), ev1 = make_float2(e1, e1);
        float2 ev2 = make_float2(e2, e2), ev3 = make_float2(e3, e3);
#pragma unroll
        for (int j = 0; j < 4; j++) {
            acc[j] = ffma2(ev0, __half22float2(p0[j]), acc[j]);
            acc[j] = ffma2(ev1, __half22float2(p1[j]), acc[j]);
            acc[j] = ffma2(ev2, __half22float2(p2[j]), acc[j]);
            acc[j] = ffma2(ev3, __half22float2(p3[j]), acc[j]);
        }
    }
    for (; i < s1; i++) {
        int r = g_row[i];
        float al = g_al1s[r * 4 + h];
        float4 raw = ((const float4*)(g_h1h + (size_t)r * 256))[lane];
        float e = __expf(lrelu(al + ad));
        z += e;
        const __half2* hp = (const __half2*)&raw;
        float2 ev = make_float2(e, e);
#pragma unroll
        for (int j = 0; j < 4; j++)
            acc[j] = ffma2(ev, __half22float2(hp[j]), acc[j]);
    }
    float inv = 1.f / (z + 1e-16f);
    float4 bv0 = *(const float4*)(b1 + lane * 8);
    float4 bv1 = *(const float4*)(b1 + lane * 8 + 4);
    float4 o0, o1;
    o0.x = elu1(acc[0].x * inv + bv0.x); o0.y = elu1(acc[0].y * inv + bv0.y);
    o0.z = elu1(acc[1].x * inv + bv0.z); o0.w = elu1(acc[1].y * inv + bv0.w);
    o1.x = elu1(acc[2].x * inv + bv1.x); o1.y = elu1(acc[2].y * inv + bv1.y);
    o1.z = elu1(acc[3].x * inv + bv1.z); o1.w = elu1(acc[3].y * inv + bv1.w);
    float4* dst = (float4*)(g_h1a + (size_t)n * 256 + lane * 8);
    dst[0] = o0;
    dst[1] = o1;
}

// ------- GEMM2: h2 = h1a[N,256] @ W2[256,64], fused layer-2 logits (al2) ----------
__global__ __launch_bounds__(256) void k_gemm2(const float* __restrict__ W2,
                                               const float* __restrict__ a2s,
                                               const float* __restrict__ a2d) {
    __shared__ float2 xs[16][128];   // flat == row-major 256 floats
    __shared__ float  red[4][16][64];
    __shared__ float  sps[16], spd[16];
    int tid = threadIdx.x;
    int j = tid & 63, q = tid >> 6;  // q: K-quarter
    int row0 = blockIdx.x * 16;
    int nrows = NN - row0; if (nrows > 16) nrows = 16;
    float2 w2[32];
#pragma unroll
    for (int k2 = 0; k2 < 32; k2++)
        w2[k2] = make_float2(W2[(q * 64 + 2 * k2) * 64 + j], W2[(q * 64 + 2 * k2 + 1) * 64 + j]);
    if (tid < 16) { sps[tid] = 0.f; spd[tid] = 0.f; }
    for (int i = tid; i < nrows * 256; i += 256)
        ((float*)xs)[i] = g_h1a[row0 * 256 + i];
    __syncthreads();
    for (int r = 0; r < nrows; r++) {
        float2 acc2 = {0.f, 0.f};
#pragma unroll
        for (int k2 = 0; k2 < 32; k2++) acc2 = ffma2(xs[r][q * 32 + k2], w2[k2], acc2);
        red[q][r][j] = acc2.x + acc2.y;
    }
    __syncthreads();
    for (int i = tid; i < nrows * 64; i += 256) {
        int r = i >> 6, jj = i & 63;
        float v = red[0][r][jj] + red[1][r][jj] + red[2][r][jj] + red[3][r][jj];
        g_h2[row0 * 64 + i] = v;
        float ps = v * a2s[jj], pd = v * a2d[jj];
#pragma unroll
        for (int off = 16; off; off >>= 1) {
            ps += __shfl_xor_sync(0xffffffffu, ps, off);
            pd += __shfl_xor_sync(0xffffffffu, pd, off);
        }
        if ((tid & 31) == 0) { atomicAdd(&sps[r], ps); atomicAdd(&spd[r], pd); }
    }
    __syncthreads();
    if (tid < nrows) {
        g_al2s[row0 + tid] = sps[tid];
        g_al2d[row0 + tid] = spd[tid];
    }
}

// --- layer-2 fused softmax + agg + node output + edge factors (warp/node, 4-wide) -
__global__ void k_agg2out(const float* __restrict__ b2, const float* __restrict__ Wn,
                          const float* __restrict__ bn, const float* __restrict__ We,
                          float* __restrict__ out) {
    int n    = (blockIdx.x * blockDim.x + threadIdx.x) >> 5;
    int lane = threadIdx.x & 31;
    if (n >= NN) return;
    int s0 = g_off[n], s1 = g_off[n + 1];
    float ad = g_al2d[n];

    float2 acc = {0.f, 0.f};
    float z = 0.f;
    int i = s0;
    for (; i + 4 <= s1; i += 4) {
        int r0 = g_row[i],     r1 = g_row[i + 1];
        int r2 = g_row[i + 2], r3 = g_row[i + 3];
        float al0 = g_al2s[r0], al1 = g_al2s[r1];
        float al2 = g_al2s[r2], al3 = g_al2s[r3];
        float2 h0 = ((const float2*)(g_h2 + (size_t)r0 * 64))[lane];
        float2 h1 = ((const float2*)(g_h2 + (size_t)r1 * 64))[lane];
        float2 h2 = ((const float2*)(g_h2 + (size_t)r2 * 64))[lane];
        float2 h3 = ((const float2*)(g_h2 + (size_t)r3 * 64))[lane];
        float e0 = __expf(lrelu(al0 + ad)), e1 = __expf(lrelu(al1 + ad));
        float e2 = __expf(lrelu(al2 + ad)), e3 = __expf(lrelu(al3 + ad));
        z += (e0 + e1) + (e2 + e3);
        acc = ffma2(make_float2(e0, e0), h0, acc);
        acc = ffma2(make_float2(e1, e1), h1, acc);
        acc = ffma2(make_float2(e2, e2), h2, acc);
        acc = ffma2(make_float2(e3, e3), h3, acc);
    }
    for (; i < s1; i++) {
        int r = g_row[i];
        float al = g_al2s[r];
        float2 h = ((const float2*)(g_h2 + (size_t)r * 64))[lane];
        float e = __expf(lrelu(al + ad));
        z += e;
        acc = ffma2(make_float2(e, e), h, acc);
    }
    float inv = 1.f / (z + 1e-16f);
    float2 bv = ((const float2*)b2)[lane];
    float2 o;   // h2a columns [2*lane, 2*lane+1]
    o.x = elu1(acc.x * inv + bv.x);
    o.y = elu1(acc.y * inv + bv.y);

    // edge-head factors: u = h2a·We[0:64], v = h2a·We[64:128]
    float2 we0 = ((const float2*)We)[lane];
    float2 we1 = ((const float2*)(We + 64))[lane];
    float up = o.x * we0.x + o.y * we0.y;
    float vp = o.x * we1.x + o.y * we1.y;
#pragma unroll
    for (int off = 16; off; off >>= 1) {
        up += __shfl_xor_sync(0xffffffffu, up, off);
        vp += __shfl_xor_sync(0xffffffffu, vp, off);
    }
    if (lane == 0) { g_u[n] = up; g_v[n] = vp; }

    // node output: out[n,:] = h2a @ Wn + bn (lane = output column)
    float accn = bn[lane];
#pragma unroll
    for (int kk = 0; kk < 32; kk++) {
        float hx = __shfl_sync(0xffffffffu, o.x, kk);
        float hy = __shfl_sync(0xffffffffu, o.y, kk);
        accn = fmaf(hx, Wn[(2 * kk) * 32 + lane], accn);
        accn = fmaf(hy, Wn[(2 * kk + 1) * 32 + lane], accn);
    }
    out[n * 32 + lane] = accn;
}

// ------- edge output part A: edge_attr contribution (overlappable) -------
__global__ void k_edgeA(const float* __restrict__ ea, const float* __restrict__ We,
                        const float* __restrict__ be, float* __restrict__ out) {
    int e = blockIdx.x * blockDim.x + threadIdx.x;
    if (e >= NE) return;
    const float4* eav = (const float4*)(ea + (size_t)e * 16);
    const float4* wev = (const float4*)(We + 128);
    float4 w0 = wev[0], w1 = wev[1], w2 = wev[2], w3 = wev[3];
    float4 e0 = eav[0], e1 = eav[1], e2 = eav[2], e3 = eav[3];
    float t = be[0];
    t += e0.x * w0.x + e0.y * w0.y + e0.z * w0.z + e0.w * w0.w;
    t += e1.x * w1.x + e1.y * w1.y + e1.z * w1.z + e1.w * w1.w;
    t += e2.x * w2.x + e2.y * w2.y + e2.z * w2.z + e2.w * w2.w;
    t += e3.x * w3.x + e3.y * w3.y + e3.z * w3.z + e3.w * w3.w;
    out[NN * 32 + e] = t;
}

// ------- edge output part B: add node factors (tail, small) -------
__global__ void k_edgeB(const int* __restrict__ ei, float* __restrict__ out) {
    int e = blockIdx.x * blockDim.x + threadIdx.x;
    if (e >= NE) return;
    int r = ei[e], c = ei[NE + e];
    out[NN * 32 + e] += g_u[r] + g_v[c];
}

// ---------------- launch ----------------
extern "C" void kernel_launch(void* const* d_in, const int* in_sizes, int n_in,
                              void* d_out, int out_size) {
    const float* x   = (const float*)d_in[0];
    const int*   ei  = (const int*)  d_in[1];
    const float* ea  = (const float*)d_in[2];
    const float* W1  = (const float*)d_in[3];
    const float* a1s = (const float*)d_in[4];
    const float* a1d = (const float*)d_in[5];
    const float* b1  = (const float*)d_in[6];
    const float* W2  = (const float*)d_in[7];
    const float* a2s = (const float*)d_in[8];
    const float* a2d = (const float*)d_in[9];
    const float* b2  = (const float*)d_in[10];
    const float* Wn  = (const float*)d_in[11];
    const float* bn  = (const float*)d_in[12];
    const float* We  = (const float*)d_in[13];
    const float* be  = (const float*)d_in[14];
    float* out = (float*)d_out;

    // one-time side stream + events (resources only; no device memory)
    static cudaStream_t s2 = [] {
        cudaStream_t s; cudaStreamCreateWithFlags(&s, cudaStreamNonBlocking); return s;
    }();
    static cudaEvent_t evFork = [] {
        cudaEvent_t e; cudaEventCreateWithFlags(&e, cudaEventDisableTiming); return e;
    }();
    static cudaEvent_t evJoin = [] {
        cudaEvent_t e; cudaEventCreateWithFlags(&e, cudaEventDisableTiming); return e;
    }();

    cudaStream_t s0 = 0;  // legacy default; the harness captures on it

    // fork
    cudaEventRecord(evFork, s0);
    cudaStreamWaitEvent(s2, evFork, 0);

    // branch 1 (capture stream): CSR build (by destination), includes self-loops
    k_deg_init<<<(NN + 255) / 256, 256, 0, s0>>>();
    k_hist   <<<(NE + 255) / 256, 256, 0, s0>>>(ei + NE);
    k_scanA  <<<NB, 256, 0, s0>>>();
    k_scanB  <<<1, 256, 0, s0>>>();
    k_scanC  <<<NB, 256, 0, s0>>>();
    k_scatter<<<(NT + 255) / 256, 256, 0, s0>>>(ei);

    // branch 2 (side stream): dense layer-1 work + edge_attr partial
    k_prew <<<1, 512, 0, s2>>>(W1, a1s, a1d);
    k_gemm1<<<(NN + 31) / 32, 256, 0, s2>>>(x, W1);
    k_edgeA<<<(NE + 255) / 256, 256, 0, s2>>>(ea, We, be, out);
    cudaEventRecord(evJoin, s2);

    // join
    cudaStreamWaitEvent(s0, evJoin, 0);

    // tail (needs CSR + gemm1)
    k_agg1   <<<(NN * 32 + 255) / 256, 256, 0, s0>>>(b1);
    k_gemm2  <<<(NN + 15) / 16, 256, 0, s0>>>(W2, a2s, a2d);
    k_agg2out<<<(NN * 32 + 255) / 256, 256, 0, s0>>>(b2, Wn, bn, We, out);
    k_edgeB  <<<(NE + 255) / 256, 256, 0, s0>>>(ei, out);
}

// round 9
// speedup vs baseline: 1.7829x; 1.0089x over previous
#include <cuda_runtime.h>
#include <cuda_fp16.h>
#include <math.h>

#define NN 50000
#define NE 800000
#define NT (NE + NN)
#define NB 196      // 196*256 = 50176 >= NN
#define NHALF 24992 // node split for tail pipelining; MUST be divisible by 16

// ---------------- scratch (static __device__, allocation-free) ----------------
__device__ __half g_h1h [NN * 256];  // layer1 pre-agg features (fp16)
__device__ float  g_h1a [NN * 256];  // layer1 output (post agg + b1 + elu), fp32
__device__ float  g_wt1[8 * 64];     // folded W1@a1 (4 src heads, 4 dst heads)
__device__ float  g_al1s[NN * 4];
__device__ float  g_al1d[NN * 4];
__device__ float  g_h2 [NN * 64];    // layer2 pre-agg features
__device__ float  g_al2s[NN];
__device__ float  g_al2d[NN];
__device__ float  g_u[NN];           // dot(h2a[n], We[0:64])
__device__ float  g_v[NN];           // dot(h2a[n], We[64:128])
__device__ int    g_deg[NN];
__device__ int    g_off[NN + 1];
__device__ int    g_cur[NN];
__device__ int    g_bsum[NB];
__device__ int    g_bbase[NB];
__device__ int    g_row[NT];         // CSR (by destination): source node per slot

__device__ __forceinline__ float lrelu(float v) { return v > 0.f ? v : 0.2f * v; }
__device__ __forceinline__ float elu1(float v)  { return v > 0.f ? v : expm1f(v); }

// packed 2xfp32 FMA (sm_103a f32x2 pipe; 2x FFMA throughput)
__device__ __forceinline__ float2 ffma2(float2 a, float2 b, float2 c) {
    float2 d;
    asm("fma.rn.f32x2 %0, %1, %2, %3;"
        : "=l"(reinterpret_cast<unsigned long long&>(d))
        : "l"(reinterpret_cast<unsigned long long&>(a)),
          "l"(reinterpret_cast<unsigned long long&>(b)),
          "l"(reinterpret_cast<unsigned long long&>(c)));
    return d;
}

// ---------------- CSR build ----------------
__global__ void k_deg_init() {
    int i = blockIdx.x * blockDim.x + threadIdx.x;
    if (i < NN) g_deg[i] = 1;  // self-loop
}

__global__ void k_hist(const int* __restrict__ col) {
    int e = blockIdx.x * blockDim.x + threadIdx.x;
    if (e < NE) atomicAdd(&g_deg[col[e]], 1);
}

__global__ void k_scanA() {  // grid NB, block 256: per-block exclusive scan
    __shared__ int ss[256];
    int b = blockIdx.x, t = threadIdx.x, i = b * 256 + t;
    int d = (i < NN) ? g_deg[i] : 0;
    ss[t] = d; __syncthreads();
    for (int o = 1; o < 256; o <<= 1) {
        int v = 0; if (t >= o) v = ss[t - o];
        __syncthreads();
        if (t >= o) ss[t] += v;
        __syncthreads();
    }
    if (i < NN) g_off[i] = ss[t] - d;
    if (t == 255) g_bsum[b] = ss[255];
}

__global__ void k_scanB() {  // 1 block 256: scan of block sums
    __shared__ int ss[256];
    int t = threadIdx.x;
    int v = (t < NB) ? g_bsum[t] : 0;
    ss[t] = v; __syncthreads();
    for (int o = 1; o < 256; o <<= 1) {
        int u = 0; if (t >= o) u = ss[t - o];
        __syncthreads();
        if (t >= o) ss[t] += u;
        __syncthreads();
    }
    if (t < NB) g_bbase[t] = ss[t] - v;
    if (t == NB - 1) g_off[NN] = ss[t];
}

__global__ void k_scanC() {  // grid NB: add block bases
    int b = blockIdx.x, i = b * 256 + threadIdx.x;
    if (i < NN) {
        int v = g_off[i] + g_bbase[b];
        g_off[i] = v; g_cur[i] = v;
    }
}

__global__ void k_scatter(const int* __restrict__ ei) {
    int e = blockIdx.x * blockDim.x + threadIdx.x;
    if (e >= NT) return;
    int r, c;
    if (e < NE) { r = ei[e]; c = ei[NE + e]; } else { r = c = e - NE; }
    int pos = atomicAdd(&g_cur[c], 1);
    g_row[pos] = r;
}

// ---------------- folded attention weights: wt1[o][k] = sum_c W1[k, h*64+c]*a[h][c] --
__global__ void k_prew(const float* __restrict__ W1, const float* __restrict__ a1s,
                       const float* __restrict__ a1d) {
    int t = threadIdx.x;   // 512 threads, 1 block
    if (t >= 512) return;
    int o = t >> 6, k = t & 63;
    int hh = o & 3;
    const float* a = (o < 4) ? a1s : a1d;
    float s = 0.f;
#pragma unroll 8
    for (int c = 0; c < 64; c++) s += W1[k * 256 + hh * 64 + c] * a[hh * 64 + c];
    g_wt1[o * 64 + k] = s;
}

// --- GEMM1: h1 = x[N,64] @ W1[64,256] (fp16 out) + fused layer-1 logits ---------
__global__ __launch_bounds__(256) void k_gemm1(const float* __restrict__ x,
                                               const float* __restrict__ W1) {
    __shared__ float2 xs[32][32];    // flat == row-major 64 floats per row
    __shared__ float  ws[8][65];     // folded weights, padded (bank-conflict-free)
    int tid = threadIdx.x;           // 0..255
    int col = tid;
    int row0 = blockIdx.x * 32;
    float2 w2[32];
#pragma unroll
    for (int k2 = 0; k2 < 32; k2++)
        w2[k2] = make_float2(W1[(2 * k2) * 256 + col], W1[(2 * k2 + 1) * 256 + col]);
    for (int i = tid; i < 512; i += 256) ws[i >> 6][i & 63] = g_wt1[i];
    int nrows = NN - row0; if (nrows > 32) nrows = 32;
    for (int i = tid; i < nrows * 64; i += 256)
        ((float*)xs)[i] = x[row0 * 64 + i];
    __syncthreads();
    for (int r = 0; r < nrows; r++) {
        float2 acc2 = {0.f, 0.f};
#pragma unroll
        for (int k2 = 0; k2 < 32; k2++) acc2 = ffma2(xs[r][k2], w2[k2], acc2);
        g_h1h[(size_t)(row0 + r) * 256 + col] = __float2half_rn(acc2.x + acc2.y);
    }
    // fused al1x: thread (r = tid>>3, o = tid&7) computes dot(x[row0+r], wt1[o])
    {
        int r = tid >> 3, o = tid & 7;
        if (r < nrows) {
            const float* xr = (const float*)xs + r * 64;
            float s = 0.f;
#pragma unroll 16
            for (int k = 0; k < 64; k++) s += xr[k] * ws[o][k];
            if (o < 4) g_al1s[(row0 + r) * 4 + o] = s;
            else       g_al1d[(row0 + r) * 4 + (o - 4)] = s;
        }
    }
}

// ------- layer-1 fused softmax + aggregation (warp/node, 8-wide batched loads) ---
__global__ void k_agg1(const float* __restrict__ b1, int n0, int n1) {
    int n    = n0 + ((blockIdx.x * blockDim.x + threadIdx.x) >> 5);
    int lane = threadIdx.x & 31;
    if (n >= n1) return;
    int s0 = g_off[n], s1 = g_off[n + 1];
    int h = lane >> 3;  // this lane's 8 columns [lane*8, lane*8+8) all in head h
    float ad = g_al1d[n * 4 + h];

    float2 acc[4] = {{0,0},{0,0},{0,0},{0,0}};
    float z = 0.f;
    int i = s0;
    for (; i + 8 <= s1; i += 8) {
        int rr[8]; float al[8]; float4 w[8];
#pragma unroll
        for (int u = 0; u < 8; u++) rr[u] = g_row[i + u];
#pragma unroll
        for (int u = 0; u < 8; u++) al[u] = g_al1s[rr[u] * 4 + h];
#pragma unroll
        for (int u = 0; u < 8; u++)
            w[u] = ((const float4*)(g_h1h + (size_t)rr[u] * 256))[lane];
#pragma unroll
        for (int u = 0; u < 8; u++) {
            float e = __expf(lrelu(al[u] + ad));
            z += e;
            const __half2* hp = (const __half2*)&w[u];
            float2 ev = make_float2(e, e);
#pragma unroll
            for (int j = 0; j < 4; j++)
                acc[j] = ffma2(ev, __half22float2(hp[j]), acc[j]);
        }
    }
    for (; i + 4 <= s1; i += 4) {
        int rr[4]; float al[4]; float4 w[4];
#pragma unroll
        for (int u = 0; u < 4; u++) rr[u] = g_row[i + u];
#pragma unroll
        for (int u = 0; u < 4; u++) al[u] = g_al1s[rr[u] * 4 + h];
#pragma unroll
        for (int u = 0; u < 4; u++)
            w[u] = ((const float4*)(g_h1h + (size_t)rr[u] * 256))[lane];
#pragma unroll
        for (int u = 0; u < 4; u++) {
            float e = __expf(lrelu(al[u] + ad));
            z += e;
            const __half2* hp = (const __half2*)&w[u];
            float2 ev = make_float2(e, e);
#pragma unroll
            for (int j = 0; j < 4; j++)
                acc[j] = ffma2(ev, __half22float2(hp[j]), acc[j]);
        }
    }
    for (; i < s1; i++) {
        int r = g_row[i];
        float al = g_al1s[r * 4 + h];
        float4 raw = ((const float4*)(g_h1h + (size_t)r * 256))[lane];
        float e = __expf(lrelu(al + ad));
        z += e;
        const __half2* hp = (const __half2*)&raw;
        float2 ev = make_float2(e, e);
#pragma unroll
        for (int j = 0; j < 4; j++)
            acc[j] = ffma2(ev, __half22float2(hp[j]), acc[j]);
    }
    float inv = 1.f / (z + 1e-16f);
    float4 bv0 = *(const float4*)(b1 + lane * 8);
    float4 bv1 = *(const float4*)(b1 + lane * 8 + 4);
    float4 o0, o1;
    o0.x = elu1(acc[0].x * inv + bv0.x); o0.y = elu1(acc[0].y * inv + bv0.y);
    o0.z = elu1(acc[1].x * inv + bv0.z); o0.w = elu1(acc[1].y * inv + bv0.w);
    o1.x = elu1(acc[2].x * inv + bv1.x); o1.y = elu1(acc[2].y * inv + bv1.y);
    o1.z = elu1(acc[3].x * inv + bv1.z); o1.w = elu1(acc[3].y * inv + bv1.w);
    float4* dst = (float4*)(g_h1a + (size_t)n * 256 + lane * 8);
    dst[0] = o0;
    dst[1] = o1;
}

// ------- GEMM2: h2 = h1a[N,256] @ W2[256,64], fused layer-2 logits (al2) ----------
__global__ __launch_bounds__(256) void k_gemm2(const float* __restrict__ W2,
                                               const float* __restrict__ a2s,
                                               const float* __restrict__ a2d, int base) {
    __shared__ float2 xs[16][128];   // flat == row-major 256 floats
    __shared__ float  red[4][16][64];
    __shared__ float  sps[16], spd[16];
    int tid = threadIdx.x;
    int j = tid & 63, q = tid >> 6;  // q: K-quarter
    int row0 = base + blockIdx.x * 16;
    int nrows = NN - row0; if (nrows > 16) nrows = 16;
    float2 w2[32];
#pragma unroll
    for (int k2 = 0; k2 < 32; k2++)
        w2[k2] = make_float2(W2[(q * 64 + 2 * k2) * 64 + j], W2[(q * 64 + 2 * k2 + 1) * 64 + j]);
    if (tid < 16) { sps[tid] = 0.f; spd[tid] = 0.f; }
    for (int i = tid; i < nrows * 256; i += 256)
        ((float*)xs)[i] = g_h1a[row0 * 256 + i];
    __syncthreads();
    for (int r = 0; r < nrows; r++) {
        float2 acc2 = {0.f, 0.f};
#pragma unroll
        for (int k2 = 0; k2 < 32; k2++) acc2 = ffma2(xs[r][q * 32 + k2], w2[k2], acc2);
        red[q][r][j] = acc2.x + acc2.y;
    }
    __syncthreads();
    for (int i = tid; i < nrows * 64; i += 256) {
        int r = i >> 6, jj = i & 63;
        float v = red[0][r][jj] + red[1][r][jj] + red[2][r][jj] + red[3][r][jj];
        g_h2[row0 * 64 + i] = v;
        float ps = v * a2s[jj], pd = v * a2d[jj];
#pragma unroll
        for (int off = 16; off; off >>= 1) {
            ps += __shfl_xor_sync(0xffffffffu, ps, off);
            pd += __shfl_xor_sync(0xffffffffu, pd, off);
        }
        if ((tid & 31) == 0) { atomicAdd(&sps[r], ps); atomicAdd(&spd[r], pd); }
    }
    __syncthreads();
    if (tid < nrows) {
        g_al2s[row0 + tid] = sps[tid];
        g_al2d[row0 + tid] = spd[tid];
    }
}

// --- layer-2 fused softmax + agg + node output + edge factors (warp/node, 8-wide) -
__global__ void k_agg2out(const float* __restrict__ b2, const float* __restrict__ Wn,
                          const float* __restrict__ bn, const float* __restrict__ We,
                          float* __restrict__ out) {
    int n    = (blockIdx.x * blockDim.x + threadIdx.x) >> 5;
    int lane = threadIdx.x & 31;
    if (n >= NN) return;
    int s0 = g_off[n], s1 = g_off[n + 1];
    float ad = g_al2d[n];

    float2 acc = {0.f, 0.f};
    float z = 0.f;
    int i = s0;
    for (; i + 8 <= s1; i += 8) {
        int rr[8]; float al[8]; float2 hh[8];
#pragma unroll
        for (int u = 0; u < 8; u++) rr[u] = g_row[i + u];
#pragma unroll
        for (int u = 0; u < 8; u++) al[u] = g_al2s[rr[u]];
#pragma unroll
        for (int u = 0; u < 8; u++)
            hh[u] = ((const float2*)(g_h2 + (size_t)rr[u] * 64))[lane];
#pragma unroll
        for (int u = 0; u < 8; u++) {
            float e = __expf(lrelu(al[u] + ad));
            z += e;
            acc = ffma2(make_float2(e, e), hh[u], acc);
        }
    }
    for (; i + 4 <= s1; i += 4) {
        int rr[4]; float al[4]; float2 hh[4];
#pragma unroll
        for (int u = 0; u < 4; u++) rr[u] = g_row[i + u];
#pragma unroll
        for (int u = 0; u < 4; u++) al[u] = g_al2s[rr[u]];
#pragma unroll
        for (int u = 0; u < 4; u++)
            hh[u] = ((const float2*)(g_h2 + (size_t)rr[u] * 64))[lane];
#pragma unroll
        for (int u = 0; u < 4; u++) {
            float e = __expf(lrelu(al[u] + ad));
            z += e;
            acc = ffma2(make_float2(e, e), hh[u], acc);
        }
    }
    for (; i < s1; i++) {
        int r = g_row[i];
        float al = g_al2s[r];
        float2 h = ((const float2*)(g_h2 + (size_t)r * 64))[lane];
        float e = __expf(lrelu(al + ad));
        z += e;
        acc = ffma2(make_float2(e, e), h, acc);
    }
    float inv = 1.f / (z + 1e-16f);
    float2 bv = ((const float2*)b2)[lane];
    float2 o;   // h2a columns [2*lane, 2*lane+1]
    o.x = elu1(acc.x * inv + bv.x);
    o.y = elu1(acc.y * inv + bv.y);

    // edge-head factors: u = h2a·We[0:64], v = h2a·We[64:128]
    float2 we0 = ((const float2*)We)[lane];
    float2 we1 = ((const float2*)(We + 64))[lane];
    float up = o.x * we0.x + o.y * we0.y;
    float vp = o.x * we1.x + o.y * we1.y;
#pragma unroll
    for (int off = 16; off; off >>= 1) {
        up += __shfl_xor_sync(0xffffffffu, up, off);
        vp += __shfl_xor_sync(0xffffffffu, vp, off);
    }
    if (lane == 0) { g_u[n] = up; g_v[n] = vp; }

    // node output: out[n,:] = h2a @ Wn + bn (lane = output column)
    float accn = bn[lane];
#pragma unroll
    for (int kk = 0; kk < 32; kk++) {
        float hx = __shfl_sync(0xffffffffu, o.x, kk);
        float hy = __shfl_sync(0xffffffffu, o.y, kk);
        accn = fmaf(hx, Wn[(2 * kk) * 32 + lane], accn);
        accn = fmaf(hy, Wn[(2 * kk + 1) * 32 + lane], accn);
    }
    out[n * 32 + lane] = accn;
}

// ------- edge output part A: edge_attr contribution (overlappable) -------
__global__ void k_edgeA(const float* __restrict__ ea, const float* __restrict__ We,
                        const float* __restrict__ be, float* __restrict__ out) {
    int e = blockIdx.x * blockDim.x + threadIdx.x;
    if (e >= NE) return;
    const float4* eav = (const float4*)(ea + (size_t)e * 16);
    const float4* wev = (const float4*)(We + 128);
    float4 w0 = wev[0], w1 = wev[1], w2 = wev[2], w3 = wev[3];
    float4 e0 = eav[0], e1 = eav[1], e2 = eav[2], e3 = eav[3];
    float t = be[0];
    t += e0.x * w0.x + e0.y * w0.y + e0.z * w0.z + e0.w * w0.w;
    t += e1.x * w1.x + e1.y * w1.y + e1.z * w1.z + e1.w * w1.w;
    t += e2.x * w2.x + e2.y * w2.y + e2.z * w2.z + e2.w * w2.w;
    t += e3.x * w3.x + e3.y * w3.y + e3.z * w3.z + e3.w * w3.w;
    out[NN * 32 + e] = t;
}

// ------- edge output part B: add node factors (tail, small) -------
__global__ void k_edgeB(const int* __restrict__ ei, float* __restrict__ out) {
    int e = blockIdx.x * blockDim.x + threadIdx.x;
    if (e >= NE) return;
    int r = ei[e], c = ei[NE + e];
    out[NN * 32 + e] += g_u[r] + g_v[c];
}

// ---------------- launch ----------------
extern "C" void kernel_launch(void* const* d_in, const int* in_sizes, int n_in,
                              void* d_out, int out_size) {
    const float* x   = (const float*)d_in[0];
    const int*   ei  = (const int*)  d_in[1];
    const float* ea  = (const float*)d_in[2];
    const float* W1  = (const float*)d_in[3];
    const float* a1s = (const float*)d_in[4];
    const float* a1d = (const float*)d_in[5];
    const float* b1  = (const float*)d_in[6];
    const float* W2  = (const float*)d_in[7];
    const float* a2s = (const float*)d_in[8];
    const float* a2d = (const float*)d_in[9];
    const float* b2  = (const float*)d_in[10];
    const float* Wn  = (const float*)d_in[11];
    const float* bn  = (const float*)d_in[12];
    const float* We  = (const float*)d_in[13];
    const float* be  = (const float*)d_in[14];
    float* out = (float*)d_out;

    // one-time side stream + events (resources only; no device memory)
    static cudaStream_t s2 = [] {
        cudaStream_t s; cudaStreamCreateWithFlags(&s, cudaStreamNonBlocking); return s;
    }();
    static cudaEvent_t evFork = [] {
        cudaEvent_t e; cudaEventCreateWithFlags(&e, cudaEventDisableTiming); return e;
    }();
    static cudaEvent_t evGemm1 = [] {
        cudaEvent_t e; cudaEventCreateWithFlags(&e, cudaEventDisableTiming); return e;
    }();
    static cudaEvent_t evA = [] {
        cudaEvent_t e; cudaEventCreateWithFlags(&e, cudaEventDisableTiming); return e;
    }();
    static cudaEvent_t evS2 = [] {
        cudaEvent_t e; cudaEventCreateWithFlags(&e, cudaEventDisableTiming); return e;
    }();

    cudaStream_t s0 = 0;  // legacy default; the harness captures on it

    // fork
    cudaEventRecord(evFork, s0);
    cudaStreamWaitEvent(s2, evFork, 0);

    // enqueue order puts k_gemm1 4th (so ncu's fixed launch-index capture hits it)
    k_deg_init<<<(NN + 255) / 256, 256, 0, s0>>>();                       // 1
    k_hist    <<<(NE + 255) / 256, 256, 0, s0>>>(ei + NE);                // 2
    k_prew    <<<1, 512, 0, s2>>>(W1, a1s, a1d);                          // 3
    k_gemm1   <<<(NN + 31) / 32, 256, 0, s2>>>(x, W1);                    // 4
    cudaEventRecord(evGemm1, s2);
    k_edgeA   <<<(NE + 255) / 256, 256, 0, s2>>>(ea, We, be, out);        // 5
    k_scanA   <<<NB, 256, 0, s0>>>();                                     // 6
    k_scanB   <<<1, 256, 0, s0>>>();                                      // 7
    k_scanC   <<<NB, 256, 0, s0>>>();                                     // 8
    k_scatter <<<(NT + 255) / 256, 256, 0, s0>>>(ei);                     // 9

    // tail: pipelined agg1 / gemm2 halves (NHALF divisible by 16 — full coverage)
    cudaStreamWaitEvent(s0, evGemm1, 0);
    k_agg1 <<<(NHALF * 32 + 255) / 256, 256, 0, s0>>>(b1, 0, NHALF);      // 10
    cudaEventRecord(evA, s0);
    k_agg1 <<<((NN - NHALF) * 32 + 255) / 256, 256, 0, s0>>>(b1, NHALF, NN); // 11
    cudaStreamWaitEvent(s2, evA, 0);
    k_gemm2<<<NHALF / 16, 256, 0, s2>>>(W2, a2s, a2d, 0);                 // 12  (24992/16 = 1562 exact)
    cudaEventRecord(evS2, s2);
    k_gemm2<<<(NN - NHALF + 15) / 16, 256, 0, s0>>>(W2, a2s, a2d, NHALF); // 13  (25008/16 = 1563 exact)
    cudaStreamWaitEvent(s0, evS2, 0);
    k_agg2out<<<(NN * 32 + 255) / 256, 256, 0, s0>>>(b2, Wn, bn, We, out); // 14
    k_edgeB  <<<(NE + 255) / 256, 256, 0, s0>>>(ei, out);                  // 15
}